// round 3
// baseline (speedup 1.0000x reference)
#include <cuda_runtime.h>
#include <cuda_bf16.h>

// Problem constants
// B=8, NK=NQ=2048, DK=DQ=DV=256, H=1024

#define BM 128
#define BN 128
#define BK 16
#define TM 8
#define TN 8
#define PAD 4

// Scratch (alloc-free rule: __device__ globals)
__device__ float g_Wk[8u * 2048u * 1024u];                 // 64 MB
__device__ float g_Wq[8u * 2048u * 1024u];                 // 64 MB
__device__ float g_Wv[8u * 2048u * 1024u];                 // 64 MB
__device__ float g_dist[(size_t)8 * 2048 * 2048];          // 128 MB
__device__ float g_ctx[8u * 2048u * 1024u];                // 64 MB

// ---------------------------------------------------------------------------
// NT GEMM: C[M,N] = A[M,K] * B[N,K]^T   (both operands K-contiguous)
// EPI: 0 = +bias[n], 1 = *scale, 2 = none
// ---------------------------------------------------------------------------
template <int EPI>
__global__ __launch_bounds__(256) void gemm_nt(
    const float* __restrict__ Ag, const float* __restrict__ Bg,
    float* __restrict__ Cg, const float* __restrict__ bias,
    int M, int N, int K, float scale,
    long long sA, long long sB, long long sC)
{
    const float* A = Ag + (long long)blockIdx.z * sA;
    const float* Bm = Bg + (long long)blockIdx.z * sB;
    float* C = Cg + (long long)blockIdx.z * sC;

    __shared__ float As[BK][BM + PAD];
    __shared__ float Bs[BK][BN + PAD];

    int tid = threadIdx.x;
    int tx = tid & 15;   // 0..15 -> N microtiles
    int ty = tid >> 4;   // 0..15 -> M microtiles
    int rowC = blockIdx.y * BM;
    int colC = blockIdx.x * BN;

    float acc[TM][TN];
#pragma unroll
    for (int i = 0; i < TM; i++)
#pragma unroll
        for (int j = 0; j < TN; j++) acc[i][j] = 0.f;

    int lr = tid >> 2;         // 0..63 tile row
    int lc = (tid & 3) << 2;   // 0,4,8,12 within BK

    for (int k0 = 0; k0 < K; k0 += BK) {
#pragma unroll
        for (int s = 0; s < 2; s++) {
            int r = lr + s * 64;
            float4 va = *(const float4*)(A + (long long)(rowC + r) * K + k0 + lc);
            As[lc + 0][r] = va.x; As[lc + 1][r] = va.y;
            As[lc + 2][r] = va.z; As[lc + 3][r] = va.w;
            float4 vb = *(const float4*)(Bm + (long long)(colC + r) * K + k0 + lc);
            Bs[lc + 0][r] = vb.x; Bs[lc + 1][r] = vb.y;
            Bs[lc + 2][r] = vb.z; Bs[lc + 3][r] = vb.w;
        }
        __syncthreads();
#pragma unroll
        for (int k = 0; k < BK; k++) {
            float ra[TM], rb[TN];
#pragma unroll
            for (int i = 0; i < TM; i++) ra[i] = As[k][ty * TM + i];
#pragma unroll
            for (int j = 0; j < TN; j++) rb[j] = Bs[k][tx * TN + j];
#pragma unroll
            for (int i = 0; i < TM; i++)
#pragma unroll
                for (int j = 0; j < TN; j++) acc[i][j] += ra[i] * rb[j];
        }
        __syncthreads();
    }

#pragma unroll
    for (int i = 0; i < TM; i++) {
        int r = rowC + ty * TM + i;
#pragma unroll
        for (int j = 0; j < TN; j += 4) {
            int c = colC + tx * TN + j;
            float4 v;
            v.x = acc[i][j + 0]; v.y = acc[i][j + 1];
            v.z = acc[i][j + 2]; v.w = acc[i][j + 3];
            if (EPI == 0) {
                v.x += bias[c]; v.y += bias[c + 1];
                v.z += bias[c + 2]; v.w += bias[c + 3];
            }
            if (EPI == 1) { v.x *= scale; v.y *= scale; v.z *= scale; v.w *= scale; }
            *(float4*)(C + (long long)r * N + c) = v;
        }
    }
}

// ---------------------------------------------------------------------------
// TN GEMM: C[M,N] = A[K,M]^T * B[K,N]   (A and B both row-major over K)
// ---------------------------------------------------------------------------
template <int EPI>
__global__ __launch_bounds__(256) void gemm_tn(
    const float* __restrict__ Ag, const float* __restrict__ Bg,
    float* __restrict__ Cg, const float* __restrict__ bias,
    int M, int N, int K, float scale,
    long long sA, long long sB, long long sC)
{
    const float* A = Ag + (long long)blockIdx.z * sA;   // [K, M] row-major
    const float* Bm = Bg + (long long)blockIdx.z * sB;  // [K, N] row-major
    float* C = Cg + (long long)blockIdx.z * sC;

    __shared__ float As[BK][BM + PAD];
    __shared__ float Bs[BK][BN + PAD];

    int tid = threadIdx.x;
    int tx = tid & 15;
    int ty = tid >> 4;
    int rowC = blockIdx.y * BM;
    int colC = blockIdx.x * BN;

    float acc[TM][TN];
#pragma unroll
    for (int i = 0; i < TM; i++)
#pragma unroll
        for (int j = 0; j < TN; j++) acc[i][j] = 0.f;

    int lr = tid >> 5;          // 0..7 (K-row within tile)
    int lc = (tid & 31) << 2;   // 0..124 (col within 128)

    for (int k0 = 0; k0 < K; k0 += BK) {
#pragma unroll
        for (int s = 0; s < 2; s++) {
            int kr = lr + s * 8;
            int gr = k0 + kr;
            *(float4*)&As[kr][lc] = *(const float4*)(A + (long long)gr * M + rowC + lc);
            *(float4*)&Bs[kr][lc] = *(const float4*)(Bm + (long long)gr * N + colC + lc);
        }
        __syncthreads();
#pragma unroll
        for (int k = 0; k < BK; k++) {
            float ra[TM], rb[TN];
#pragma unroll
            for (int i = 0; i < TM; i++) ra[i] = As[k][ty * TM + i];
#pragma unroll
            for (int j = 0; j < TN; j++) rb[j] = Bs[k][tx * TN + j];
#pragma unroll
            for (int i = 0; i < TM; i++)
#pragma unroll
                for (int j = 0; j < TN; j++) acc[i][j] += ra[i] * rb[j];
        }
        __syncthreads();
    }

#pragma unroll
    for (int i = 0; i < TM; i++) {
        int r = rowC + ty * TM + i;
#pragma unroll
        for (int j = 0; j < TN; j += 4) {
            int c = colC + tx * TN + j;
            float4 v;
            v.x = acc[i][j + 0]; v.y = acc[i][j + 1];
            v.z = acc[i][j + 2]; v.w = acc[i][j + 3];
            if (EPI == 0) {
                v.x += bias[c]; v.y += bias[c + 1];
                v.z += bias[c + 2]; v.w += bias[c + 3];
            }
            if (EPI == 1) { v.x *= scale; v.y *= scale; v.z *= scale; v.w *= scale; }
            *(float4*)(C + (long long)r * N + c) = v;
        }
    }
}

// ---------------------------------------------------------------------------
// Row softmax over the last (contiguous) axis; ncols must be 2048.
// One block (256 threads) per row, 8 elements per thread, in-place.
// ---------------------------------------------------------------------------
__global__ __launch_bounds__(256) void softmax_rows(float* __restrict__ d)
{
    long long row = blockIdx.x;
    float* p = d + row * 2048ll;
    int t = threadIdx.x;

    float v[8];
    float m = -1e30f;
#pragma unroll
    for (int j = 0; j < 8; j++) {
        v[j] = p[t + (j << 8)];
        m = fmaxf(m, v[j]);
    }
#pragma unroll
    for (int o = 16; o > 0; o >>= 1) m = fmaxf(m, __shfl_xor_sync(0xffffffffu, m, o));
    __shared__ float redm[8];
    if ((t & 31) == 0) redm[t >> 5] = m;
    __syncthreads();
#pragma unroll
    for (int w = 0; w < 8; w++) m = fmaxf(m, redm[w]);

    float s = 0.f;
#pragma unroll
    for (int j = 0; j < 8; j++) {
        v[j] = __expf(v[j] - m);
        s += v[j];
    }
#pragma unroll
    for (int o = 16; o > 0; o >>= 1) s += __shfl_xor_sync(0xffffffffu, s, o);
    __shared__ float reds[8];
    if ((t & 31) == 0) reds[t >> 5] = s;
    __syncthreads();
    s = 0.f;
#pragma unroll
    for (int w = 0; w < 8; w++) s += reds[w];
    float inv = 1.f / s;
#pragma unroll
    for (int j = 0; j < 8; j++) p[t + (j << 8)] = v[j] * inv;
}

// ---------------------------------------------------------------------------
extern "C" void kernel_launch(void* const* d_in, const int* in_sizes, int n_in,
                              void* d_out, int out_size)
{
    const int Bb = 8, NK = 2048, NQ = 2048, D = 256, H = 1024;
    const float scale = 1.0f / 32.0f;  // 1/sqrt(H=1024)

    const float* KEY   = (const float*)d_in[0];
    const float* VALUE = (const float*)d_in[1];
    const float* QUERY = (const float*)d_in[2];
    const float* Wk_w  = (const float*)d_in[3];
    const float* Wk_b  = (const float*)d_in[4];
    const float* Wq_w  = (const float*)d_in[5];
    const float* Wq_b  = (const float*)d_in[6];
    const float* Wv_w  = (const float*)d_in[7];
    const float* Wv_b  = (const float*)d_in[8];
    const float* lin_w = (const float*)d_in[9];
    const float* lin_b = (const float*)d_in[10];
    float* out = (float*)d_out;

    float *Wk, *Wq, *Wv, *dist, *ctx;
    cudaGetSymbolAddress((void**)&Wk, g_Wk);
    cudaGetSymbolAddress((void**)&Wq, g_Wq);
    cudaGetSymbolAddress((void**)&Wv, g_Wv);
    cudaGetSymbolAddress((void**)&dist, g_dist);
    cudaGetSymbolAddress((void**)&ctx, g_ctx);

    dim3 thr(256);

    // Projections: [B*N, D] x [H, D]^T + bias -> [B*N, H]
    gemm_nt<0><<<dim3(H / BN, (Bb * NK) / BM, 1), thr>>>(
        KEY, Wk_w, Wk, Wk_b, Bb * NK, H, D, 1.f, 0, 0, 0);
    gemm_nt<0><<<dim3(H / BN, (Bb * NQ) / BM, 1), thr>>>(
        QUERY, Wq_w, Wq, Wq_b, Bb * NQ, H, D, 1.f, 0, 0, 0);
    gemm_nt<0><<<dim3(H / BN, (Bb * NK) / BM, 1), thr>>>(
        VALUE, Wv_w, Wv, Wv_b, Bb * NK, H, D, 1.f, 0, 0, 0);

    // dist[b,i,k] = scale * sum_h Wk[b,i,h]*Wq[b,k,h]  (batched NT)
    gemm_nt<1><<<dim3(NQ / BN, NK / BM, Bb), thr>>>(
        Wk, Wq, dist, nullptr, NK, NQ, H, scale,
        (long long)NK * H, (long long)NQ * H, (long long)NK * NQ);

    // softmax over k (last axis) in-place
    softmax_rows<<<Bb * NK, 256>>>(dist);

    // context[b,k,h] = sum_i weights[b,i,k]*Wv[b,i,h]  (batched TN)
    gemm_tn<2><<<dim3(H / BN, NQ / BM, Bb), thr>>>(
        dist, Wv, ctx, nullptr, NQ, H, NK, 1.f,
        (long long)NK * NQ, (long long)NK * H, (long long)NQ * H);

    // res = context @ lin_w^T + lin_b : [B*NQ, H] x [D, H]^T -> [B*NQ, D]
    gemm_nt<0><<<dim3(D / BN, (Bb * NQ) / BM, 1), thr>>>(
        ctx, lin_w, out, lin_b, Bb * NQ, D, H, 1.f, 0, 0, 0);
}

// round 5
// speedup vs baseline: 2.9634x; 2.9634x over previous
#include <cuda_runtime.h>
#include <cuda_bf16.h>
#include <cstdint>

// B=8, NK=NQ=2048, DK=DQ=DV=256, H=1024
#define STAGES 3

// ---------------- scratch (__device__ globals; alloc-free rule) ------------
__device__ float g_Wk[8u * 2048u * 1024u];                 // 64 MB (tf32)
__device__ float g_Wq[8u * 2048u * 1024u];                 // 64 MB (tf32)
__device__ float g_Wv[8u * 2048u * 1024u];                 // 64 MB (tf32)
__device__ float g_dist[(size_t)8 * 2048 * 2048];          // 128 MB
__device__ float g_ctx[8u * 2048u * 1024u];                // 64 MB (tf32)
// tf32-rounded copies of inputs
__device__ float g_key[8u * 2048u * 256u];
__device__ float g_val[8u * 2048u * 256u];
__device__ float g_qry[8u * 2048u * 256u];
__device__ float g_wkw[1024u * 256u];
__device__ float g_wqw[1024u * 256u];
__device__ float g_wvw[1024u * 256u];
__device__ float g_linw[256u * 1024u];

// ---------------- helpers ---------------------------------------------------
__device__ __forceinline__ float tf32r(float x) {
    float y;
    asm("cvt.rna.tf32.f32 %0, %1;" : "=f"(y) : "f"(x));
    return y;
}

__device__ __forceinline__ void cp16(void* s, const void* g) {
    uint32_t sa = (uint32_t)__cvta_generic_to_shared(s);
    asm volatile("cp.async.cg.shared.global [%0], [%1], 16;" :: "r"(sa), "l"(g));
}
#define CP_COMMIT() asm volatile("cp.async.commit_group;")
#define CP_WAIT(n)  asm volatile("cp.async.wait_group %0;" :: "n"(n))

#define MMA_TF32(c, a, b)                                                      \
    asm volatile(                                                              \
        "mma.sync.aligned.m16n8k8.row.col.f32.tf32.tf32.f32 "                  \
        "{%0,%1,%2,%3},{%4,%5,%6,%7},{%8,%9},{%0,%1,%2,%3};"                   \
        : "+f"(c[0]), "+f"(c[1]), "+f"(c[2]), "+f"(c[3])                       \
        : "r"(a[0]), "r"(a[1]), "r"(a[2]), "r"(a[3]), "r"(b[0]), "r"(b[1]))

// tf32 round pre-pass (float4 elementwise)
__global__ void cvt_tf32(const float* __restrict__ in, float* __restrict__ out, int n4) {
    int i = blockIdx.x * blockDim.x + threadIdx.x;
    if (i < n4) {
        float4 v = ((const float4*)in)[i];
        v.x = tf32r(v.x); v.y = tf32r(v.y); v.z = tf32r(v.z); v.w = tf32r(v.w);
        ((float4*)out)[i] = v;
    }
}

// ---------------------------------------------------------------------------
// TF32 tensor-core GEMM. C[M,N] = op(A) * op(B).
//  AMAJ=0: A is [M,K] row-major (K contiguous).  AMAJ=1: A is [K,M] (M contiguous), used transposed.
//  BMAJ=0: B is [N,K] row-major (NT, K contiguous). BMAJ=1: B is [K,N] (N contiguous).
//  EPI: 0 = +bias[n], 1 = *scale, 2 = none.  ROUND: tf32-round the stored C.
// CTA tile 128x128x32, 8 warps, warp tile 64x32 (m16n8k8 frags), 3-stage cp.async.
// ---------------------------------------------------------------------------
template <int AMAJ, int BMAJ, int EPI, int ROUND>
__global__ __launch_bounds__(256) void gemm_tf32(
    const float* __restrict__ Ag, const float* __restrict__ Bg,
    float* __restrict__ Cg, const float* __restrict__ bias,
    int M, int N, int K, float scale,
    long long sA, long long sB, long long sC)
{
    extern __shared__ float sm[];
    constexpr int ASTG = AMAJ ? 32 * 132 : 128 * 36;
    constexpr int BSTG = BMAJ ? 32 * 132 : 128 * 36;
    float* Abuf = sm;
    float* Bbuf = sm + STAGES * ASTG;

    const float* A  = Ag + (long long)blockIdx.z * sA;
    const float* Bm = Bg + (long long)blockIdx.z * sB;
    float* C        = Cg + (long long)blockIdx.z * sC;
    const int ldA = AMAJ ? M : K;
    const int ldB = BMAJ ? N : K;

    const int tid = threadIdx.x;
    const int lane = tid & 31;
    const int w = tid >> 5;
    const int wm = (w & 1) * 64;      // warp m-offset (2 warps in m)
    const int wn = (w >> 1) * 32;     // warp n-offset (4 warps in n)
    const int g = lane >> 2;          // 0..7
    const int t = lane & 3;           // 0..3
    const int rowC = blockIdx.y * 128;
    const int colC = blockIdx.x * 128;

    float acc[4][4][4];
#pragma unroll
    for (int mt = 0; mt < 4; mt++)
#pragma unroll
        for (int nt = 0; nt < 4; nt++)
#pragma unroll
            for (int r = 0; r < 4; r++) acc[mt][nt][r] = 0.f;

    const int T = K / 32;

    auto loadTile = [&](int kt, int stg) {
        float* as = Abuf + stg * ASTG;
        float* bs = Bbuf + stg * BSTG;
        const int k0 = kt * 32;
        if (AMAJ == 0) {
#pragma unroll
            for (int j = 0; j < 4; j++) {
                int c = tid + 256 * j; int m = c >> 3, kq = c & 7;
                cp16(as + m * 36 + kq * 4,
                     A + (long long)(rowC + m) * ldA + k0 + kq * 4);
            }
        } else {
#pragma unroll
            for (int j = 0; j < 4; j++) {
                int c = tid + 256 * j; int k = c >> 5, mq = c & 31;
                cp16(as + k * 132 + mq * 4,
                     A + (long long)(k0 + k) * ldA + rowC + mq * 4);
            }
        }
        if (BMAJ == 0) {
#pragma unroll
            for (int j = 0; j < 4; j++) {
                int c = tid + 256 * j; int n = c >> 3, kq = c & 7;
                cp16(bs + n * 36 + kq * 4,
                     Bm + (long long)(colC + n) * ldB + k0 + kq * 4);
            }
        } else {
#pragma unroll
            for (int j = 0; j < 4; j++) {
                int c = tid + 256 * j; int k = c >> 5, nq = c & 31;
                cp16(bs + k * 132 + nq * 4,
                     Bm + (long long)(k0 + k) * ldB + colC + nq * 4);
            }
        }
        CP_COMMIT();
    };

    // prologue: stages 0 and 1
    loadTile(0, 0);
    loadTile(1, 1);

    for (int kt = 0; kt < T; kt++) {
        if (kt + 2 < T) loadTile(kt + 2, (kt + 2) % STAGES);

        // wait until tile kt is resident
        if (kt + 2 < T)      { CP_WAIT(2); }
        else if (kt + 1 < T) { CP_WAIT(1); }
        else                 { CP_WAIT(0); }
        __syncthreads();

        const float* as = Abuf + (kt % STAGES) * ASTG;
        const float* bs = Bbuf + (kt % STAGES) * BSTG;

#pragma unroll
        for (int ks = 0; ks < 4; ks++) {
            uint32_t af[4][4];
#pragma unroll
            for (int mt = 0; mt < 4; mt++) {
                int r0 = wm + mt * 16 + g;
                int c0 = ks * 8 + t;
                if (AMAJ == 0) {
                    af[mt][0] = __float_as_uint(as[r0 * 36 + c0]);
                    af[mt][1] = __float_as_uint(as[(r0 + 8) * 36 + c0]);
                    af[mt][2] = __float_as_uint(as[r0 * 36 + c0 + 4]);
                    af[mt][3] = __float_as_uint(as[(r0 + 8) * 36 + c0 + 4]);
                } else {
                    af[mt][0] = __float_as_uint(as[c0 * 132 + r0]);
                    af[mt][1] = __float_as_uint(as[c0 * 132 + r0 + 8]);
                    af[mt][2] = __float_as_uint(as[(c0 + 4) * 132 + r0]);
                    af[mt][3] = __float_as_uint(as[(c0 + 4) * 132 + r0 + 8]);
                }
            }
            uint32_t bf[4][2];
#pragma unroll
            for (int nt = 0; nt < 4; nt++) {
                int n0 = wn + nt * 8 + g;
                int k0 = ks * 8 + t;
                if (BMAJ == 0) {
                    bf[nt][0] = __float_as_uint(bs[n0 * 36 + k0]);
                    bf[nt][1] = __float_as_uint(bs[n0 * 36 + k0 + 4]);
                } else {
                    bf[nt][0] = __float_as_uint(bs[k0 * 132 + n0]);
                    bf[nt][1] = __float_as_uint(bs[(k0 + 4) * 132 + n0]);
                }
            }
#pragma unroll
            for (int mt = 0; mt < 4; mt++)
#pragma unroll
                for (int nt = 0; nt < 4; nt++)
                    MMA_TF32(acc[mt][nt], af[mt], bf[nt]);
        }
        __syncthreads();
    }

    // epilogue
#pragma unroll
    for (int mt = 0; mt < 4; mt++) {
        int r = rowC + wm + mt * 16 + g;
#pragma unroll
        for (int nt = 0; nt < 4; nt++) {
            int n0 = colC + wn + nt * 8 + 2 * t;
            float x0 = acc[mt][nt][0], x1 = acc[mt][nt][1];
            float x2 = acc[mt][nt][2], x3 = acc[mt][nt][3];
            if (EPI == 0) {
                float b0 = bias[n0], b1 = bias[n0 + 1];
                x0 += b0; x1 += b1; x2 += b0; x3 += b1;
            }
            if (EPI == 1) { x0 *= scale; x1 *= scale; x2 *= scale; x3 *= scale; }
            if (ROUND) { x0 = tf32r(x0); x1 = tf32r(x1); x2 = tf32r(x2); x3 = tf32r(x3); }
            float2 v0 = make_float2(x0, x1);
            float2 v1 = make_float2(x2, x3);
            *(float2*)(C + (long long)r * N + n0) = v0;
            *(float2*)(C + (long long)(r + 8) * N + n0) = v1;
        }
    }
}

// ---------------------------------------------------------------------------
// Row softmax over contiguous last axis (2048 cols), tf32-rounded output.
// ---------------------------------------------------------------------------
__global__ __launch_bounds__(256) void softmax_rows(float* __restrict__ d)
{
    long long row = blockIdx.x;
    float* p = d + row * 2048ll;
    int t = threadIdx.x;

    float v[8];
    float m = -1e30f;
#pragma unroll
    for (int j = 0; j < 8; j++) {
        v[j] = p[t + (j << 8)];
        m = fmaxf(m, v[j]);
    }
#pragma unroll
    for (int o = 16; o > 0; o >>= 1) m = fmaxf(m, __shfl_xor_sync(0xffffffffu, m, o));
    __shared__ float redm[8];
    if ((t & 31) == 0) redm[t >> 5] = m;
    __syncthreads();
#pragma unroll
    for (int wv2 = 0; wv2 < 8; wv2++) m = fmaxf(m, redm[wv2]);

    float s = 0.f;
#pragma unroll
    for (int j = 0; j < 8; j++) {
        v[j] = __expf(v[j] - m);
        s += v[j];
    }
#pragma unroll
    for (int o = 16; o > 0; o >>= 1) s += __shfl_xor_sync(0xffffffffu, s, o);
    __shared__ float reds[8];
    if ((t & 31) == 0) reds[t >> 5] = s;
    __syncthreads();
    s = 0.f;
#pragma unroll
    for (int wv2 = 0; wv2 < 8; wv2++) s += reds[wv2];
    float inv = 1.f / s;
#pragma unroll
    for (int j = 0; j < 8; j++) p[t + (j << 8)] = tf32r(v[j] * inv);
}

// ---------------------------------------------------------------------------
extern "C" void kernel_launch(void* const* d_in, const int* in_sizes, int n_in,
                              void* d_out, int out_size)
{
    const int Bb = 8, NK = 2048, NQ = 2048, D = 256, H = 1024;
    const float scale = 1.0f / 32.0f;  // 1/sqrt(1024)

    const float* KEY   = (const float*)d_in[0];
    const float* VALUE = (const float*)d_in[1];
    const float* QUERY = (const float*)d_in[2];
    const float* Wk_w  = (const float*)d_in[3];
    const float* Wk_b  = (const float*)d_in[4];
    const float* Wq_w  = (const float*)d_in[5];
    const float* Wq_b  = (const float*)d_in[6];
    const float* Wv_w  = (const float*)d_in[7];
    const float* Wv_b  = (const float*)d_in[8];
    const float* lin_w = (const float*)d_in[9];
    const float* lin_b = (const float*)d_in[10];
    float* out = (float*)d_out;

    float *Wk, *Wq, *Wv, *dist, *ctx, *key, *val, *qry, *wkw, *wqw, *wvw, *linw;
    cudaGetSymbolAddress((void**)&Wk, g_Wk);
    cudaGetSymbolAddress((void**)&Wq, g_Wq);
    cudaGetSymbolAddress((void**)&Wv, g_Wv);
    cudaGetSymbolAddress((void**)&dist, g_dist);
    cudaGetSymbolAddress((void**)&ctx, g_ctx);
    cudaGetSymbolAddress((void**)&key, g_key);
    cudaGetSymbolAddress((void**)&val, g_val);
    cudaGetSymbolAddress((void**)&qry, g_qry);
    cudaGetSymbolAddress((void**)&wkw, g_wkw);
    cudaGetSymbolAddress((void**)&wqw, g_wqw);
    cudaGetSymbolAddress((void**)&wvw, g_wvw);
    cudaGetSymbolAddress((void**)&linw, g_linw);

    // allow >48KB dynamic smem for each instantiation (capture-safe, idempotent)
    const int SM_NT = STAGES * (128 * 36 + 128 * 36) * 4;   // 110592 B
    const int SM_TT = STAGES * (32 * 132 + 32 * 132) * 4;   // 101376 B
    (void)cudaFuncSetAttribute(gemm_tf32<0,0,0,1>, cudaFuncAttributeMaxDynamicSharedMemorySize, SM_NT);
    (void)cudaFuncSetAttribute(gemm_tf32<0,0,1,0>, cudaFuncAttributeMaxDynamicSharedMemorySize, SM_NT);
    (void)cudaFuncSetAttribute(gemm_tf32<1,1,2,1>, cudaFuncAttributeMaxDynamicSharedMemorySize, SM_TT);
    (void)cudaFuncSetAttribute(gemm_tf32<0,0,0,0>, cudaFuncAttributeMaxDynamicSharedMemorySize, SM_NT);

    // tf32 pre-round inputs
    {
        int n4;
        n4 = Bb * NK * D / 4;  cvt_tf32<<<(n4 + 255) / 256, 256>>>(KEY, key, n4);
        n4 = Bb * NK * D / 4;  cvt_tf32<<<(n4 + 255) / 256, 256>>>(VALUE, val, n4);
        n4 = Bb * NQ * D / 4;  cvt_tf32<<<(n4 + 255) / 256, 256>>>(QUERY, qry, n4);
        n4 = H * D / 4;        cvt_tf32<<<(n4 + 255) / 256, 256>>>(Wk_w, wkw, n4);
        n4 = H * D / 4;        cvt_tf32<<<(n4 + 255) / 256, 256>>>(Wq_w, wqw, n4);
        n4 = H * D / 4;        cvt_tf32<<<(n4 + 255) / 256, 256>>>(Wv_w, wvw, n4);
        n4 = D * H / 4;        cvt_tf32<<<(n4 + 255) / 256, 256>>>(lin_w, linw, n4);
    }

    dim3 thr(256);

    // Projections: [B*N, 256] x [1024, 256]^T + bias -> [B*N, 1024] (tf32-rounded)
    gemm_tf32<0,0,0,1><<<dim3(H / 128, (Bb * NK) / 128, 1), thr, SM_NT>>>(
        key, wkw, Wk, Wk_b, Bb * NK, H, D, 1.f, 0, 0, 0);
    gemm_tf32<0,0,0,1><<<dim3(H / 128, (Bb * NQ) / 128, 1), thr, SM_NT>>>(
        qry, wqw, Wq, Wq_b, Bb * NQ, H, D, 1.f, 0, 0, 0);
    gemm_tf32<0,0,0,1><<<dim3(H / 128, (Bb * NK) / 128, 1), thr, SM_NT>>>(
        val, wvw, Wv, Wv_b, Bb * NK, H, D, 1.f, 0, 0, 0);

    // dist[b,i,k] = scale * sum_h Wk[b,i,h]*Wq[b,k,h]  (batched NT)
    gemm_tf32<0,0,1,0><<<dim3(NQ / 128, NK / 128, Bb), thr, SM_NT>>>(
        Wk, Wq, dist, nullptr, NK, NQ, H, scale,
        (long long)NK * H, (long long)NQ * H, (long long)NK * NQ);

    // softmax over k (last axis), writes tf32-rounded weights
    softmax_rows<<<Bb * NK, 256>>>(dist);

    // context[b,k,h] = sum_i weights[b,i,k]*Wv[b,i,h]  (batched TN, tf32-rounded)
    gemm_tf32<1,1,2,1><<<dim3(H / 128, NQ / 128, Bb), thr, SM_TT>>>(
        dist, Wv, ctx, nullptr, NQ, H, NK, 1.f,
        (long long)NK * NQ, (long long)NK * H, (long long)NQ * H);

    // res = context @ lin_w^T + lin_b : [B*NQ, 1024] x [256, 1024]^T -> [B*NQ, 256]
    gemm_tf32<0,0,0,0><<<dim3(D / 128, (Bb * NQ) / 128, 1), thr, SM_NT>>>(
        ctx, linw, out, lin_b, Bb * NQ, D, H, 1.f, 0, 0, 0);
}

// round 7
// speedup vs baseline: 7.0994x; 2.3957x over previous
#include <cuda_runtime.h>
#include <cuda_fp16.h>
#include <cstdint>

// B=8, NK=NQ=2048, D=256, H=1024
// All GEMMs: C[M,N] = A[M,K] * B[N,K]^T, fp16 operands via mma.sync m16n8k16, fp32 accum.

#define KC     64                    // K elems per chunk (128 B fp16 per row)
#define NSTG   3
#define TILE_B 16384                 // 128 rows * 128 B
#define STG_B  (2 * TILE_B)
#define SMEM_REQ (NSTG * STG_B)      // 98304 B

// ---------------- scratch (__device__ globals) ------------------------------
__device__ __half h_key [8u*2048u*256u];
__device__ __half h_val [8u*2048u*256u];
__device__ __half h_qry [8u*2048u*256u];
__device__ __half h_wkw [1024u*256u];
__device__ __half h_wqw [1024u*256u];
__device__ __half h_wvw [1024u*256u];
__device__ __half h_linw[256u*1024u];
__device__ __half h_Wk  [8u*2048u*1024u];
__device__ __half h_Wq  [8u*2048u*1024u];
__device__ __half h_Wv  [8u*2048u*1024u];
__device__ __half h_WvT [8u*1024u*2048u];
__device__ float  g_dist[(size_t)8*2048*2048];
__device__ __half h_w   [(size_t)8*2048*2048];
__device__ __half h_wT  [(size_t)8*2048*2048];
__device__ __half h_ctx [8u*2048u*1024u];

// ---------------- PTX helpers ----------------------------------------------
__device__ __forceinline__ uint32_t smem_u32(const void* p) {
    uint32_t a;
    asm("{ .reg .u64 t; cvta.to.shared.u64 t, %1; cvt.u32.u64 %0, t; }" : "=r"(a) : "l"(p));
    return a;
}
__device__ __forceinline__ void cp16s(uint32_t s, const void* g) {
    asm volatile("cp.async.cg.shared.global [%0], [%1], 16;" :: "r"(s), "l"(g));
}
#define CP_COMMIT() asm volatile("cp.async.commit_group;")
#define CP_WAIT(n)  asm volatile("cp.async.wait_group %0;" :: "n"(n))

__device__ __forceinline__ void ldsm4(uint32_t& r0, uint32_t& r1, uint32_t& r2, uint32_t& r3,
                                      uint32_t addr) {
    asm volatile("ldmatrix.sync.aligned.m8n8.x4.shared.b16 {%0,%1,%2,%3}, [%4];"
                 : "=r"(r0), "=r"(r1), "=r"(r2), "=r"(r3) : "r"(addr));
}
#define MMA_F16(c, a, b)                                                       \
    asm volatile(                                                              \
        "mma.sync.aligned.m16n8k16.row.col.f32.f16.f16.f32 "                   \
        "{%0,%1,%2,%3},{%4,%5,%6,%7},{%8,%9},{%0,%1,%2,%3};"                   \
        : "+f"(c[0]), "+f"(c[1]), "+f"(c[2]), "+f"(c[3])                       \
        : "r"(a[0]), "r"(a[1]), "r"(a[2]), "r"(a[3]), "r"(b[0]), "r"(b[1]))

// ---------------------------------------------------------------------------
// fp16 NT GEMM: tile 128x128, BK=64, 3-stage cp.async, 8 warps @ 64x32.
// EPI: 0 = +bias -> half, 1 = *scale -> float, 2 = +bias -> float, 3 = plain -> half
// ---------------------------------------------------------------------------
template <int EPI>
__global__ __launch_bounds__(256, 2) void gemm_h(
    const __half* __restrict__ Ag, const __half* __restrict__ Bg,
    void* __restrict__ Cg, const float* __restrict__ bias,
    int M, int N, int K, float scale,
    long long sA, long long sB, long long sC)
{
    extern __shared__ char smem_raw[];
    const uint32_t sb = smem_u32(smem_raw);

    const int tid = threadIdx.x, lane = tid & 31, w = tid >> 5;
    const int wm = (w & 1) * 64;      // 2 warps over M
    const int wn = (w >> 1) * 32;     // 4 warps over N
    const __half* A  = Ag + (long long)blockIdx.z * sA;
    const __half* Bm = Bg + (long long)blockIdx.z * sB;
    const long long cb = (long long)blockIdx.z * sC;
    const int m0 = blockIdx.y * 128, n0 = blockIdx.x * 128;

    float acc[4][4][4];
#pragma unroll
    for (int mt = 0; mt < 4; mt++)
#pragma unroll
        for (int nt = 0; nt < 4; nt++)
#pragma unroll
            for (int r = 0; r < 4; r++) acc[mt][nt][r] = 0.f;

    // ldmatrix per-lane invariants
    const int laneRowA = lane & 15;            // row within 16-row block
    const int granA    = lane >> 4;            // 0/1 -> k granule half
    const int swA      = laneRowA & 7;
    const int laneRowB = ((lane >> 4) << 3) + (lane & 7);  // row within 16-n block
    const int granB    = (lane >> 3) & 1;
    const int swB      = lane & 7;

    auto load_chunk = [&](int c) {
        const int st = c % NSTG;
        const uint32_t sa  = sb + st * STG_B;
        const uint32_t sbu = sa + TILE_B;
        const char* ap = (const char*)A  + ((long long)m0 * K + (long long)c * KC) * 2;
        const char* bp = (const char*)Bm + ((long long)n0 * K + (long long)c * KC) * 2;
#pragma unroll
        for (int j = 0; j < 4; j++) {
            int gi = tid + 256 * j;
            int r = gi >> 3, g = gi & 7;
            uint32_t sw = (uint32_t)((g ^ (r & 7)) << 4) + (uint32_t)(r << 7);
            cp16s(sa  + sw, ap + (long long)r * K * 2 + g * 16);
            cp16s(sbu + sw, bp + (long long)r * K * 2 + g * 16);
        }
        CP_COMMIT();
    };

    const int C = K / KC;
    load_chunk(0); load_chunk(1);

    for (int c = 0; c < C; c++) {
        if (c + 2 < C) load_chunk(c + 2);

        if (c + 2 < C)      { CP_WAIT(2); }
        else if (c + 1 < C) { CP_WAIT(1); }
        else                { CP_WAIT(0); }
        __syncthreads();

        const uint32_t sa  = sb + (c % NSTG) * STG_B;
        const uint32_t sbu = sa + TILE_B;

#pragma unroll
        for (int ks = 0; ks < 4; ks++) {
            // B fragments: 2 x ldmatrix.x4 covering 4 n-tiles of 8
            uint32_t bf[4][2];
#pragma unroll
            for (int np = 0; np < 2; np++) {
                int rB = wn + np * 16 + laneRowB;
                uint32_t addr = sbu + (uint32_t)(rB << 7)
                              + (uint32_t)((((ks << 1) + granB) ^ swB) << 4);
                ldsm4(bf[2 * np][0], bf[2 * np][1], bf[2 * np + 1][0], bf[2 * np + 1][1], addr);
            }
#pragma unroll
            for (int mt = 0; mt < 4; mt++) {
                int rA = wm + mt * 16 + laneRowA;
                uint32_t addr = sa + (uint32_t)(rA << 7)
                              + (uint32_t)((((ks << 1) + granA) ^ swA) << 4);
                uint32_t af[4];
                ldsm4(af[0], af[1], af[2], af[3], addr);
#pragma unroll
                for (int nt = 0; nt < 4; nt++)
                    MMA_F16(acc[mt][nt], af, bf[nt]);
            }
        }
        __syncthreads();
    }

    // epilogue: c-frag lane = 4*gr + t -> (row gr, col 2t) / (row gr+8, col 2t)
    const int gr = lane >> 2, t4 = lane & 3;
#pragma unroll
    for (int mt = 0; mt < 4; mt++) {
        int r = m0 + wm + mt * 16 + gr;
#pragma unroll
        for (int nt = 0; nt < 4; nt++) {
            int cidx = n0 + wn + nt * 8 + 2 * t4;
            float x0 = acc[mt][nt][0], x1 = acc[mt][nt][1];
            float x2 = acc[mt][nt][2], x3 = acc[mt][nt][3];
            if (EPI == 0 || EPI == 2) {
                float b0 = bias[cidx], b1 = bias[cidx + 1];
                x0 += b0; x1 += b1; x2 += b0; x3 += b1;
            }
            if (EPI == 1) { x0 *= scale; x1 *= scale; x2 *= scale; x3 *= scale; }
            if (EPI == 1 || EPI == 2) {
                float* Co = (float*)Cg + cb;
                *(float2*)(Co + (long long)r * N + cidx) = make_float2(x0, x1);
                *(float2*)(Co + (long long)(r + 8) * N + cidx) = make_float2(x2, x3);
            } else {
                __half* Co = (__half*)Cg + cb;
                *(__half2*)(Co + (long long)r * N + cidx) = __floats2half2_rn(x0, x1);
                *(__half2*)(Co + (long long)(r + 8) * N + cidx) = __floats2half2_rn(x2, x3);
            }
        }
    }
}

// ---------------------------------------------------------------------------
// Row softmax: fp32 logits [rows,2048] -> fp16 weights
// ---------------------------------------------------------------------------
__global__ __launch_bounds__(256) void softmax_h(const float* __restrict__ d,
                                                 __half* __restrict__ o)
{
    long long row = blockIdx.x;
    const float* p = d + row * 2048ll;
    __half* q = o + row * 2048ll;
    int t = threadIdx.x;

    float v[8];
    float m = -1e30f;
#pragma unroll
    for (int j = 0; j < 8; j++) { v[j] = p[t + (j << 8)]; m = fmaxf(m, v[j]); }
#pragma unroll
    for (int of = 16; of > 0; of >>= 1) m = fmaxf(m, __shfl_xor_sync(0xffffffffu, m, of));
    __shared__ float redm[8];
    if ((t & 31) == 0) redm[t >> 5] = m;
    __syncthreads();
#pragma unroll
    for (int w2 = 0; w2 < 8; w2++) m = fmaxf(m, redm[w2]);

    float s = 0.f;
#pragma unroll
    for (int j = 0; j < 8; j++) { v[j] = __expf(v[j] - m); s += v[j]; }
#pragma unroll
    for (int of = 16; of > 0; of >>= 1) s += __shfl_xor_sync(0xffffffffu, s, of);
    __shared__ float reds[8];
    if ((t & 31) == 0) reds[t >> 5] = s;
    __syncthreads();
    s = 0.f;
#pragma unroll
    for (int w2 = 0; w2 < 8; w2++) s += reds[w2];
    float inv = 1.f / s;
#pragma unroll
    for (int j = 0; j < 8; j++) q[t + (j << 8)] = __float2half_rn(v[j] * inv);
}

// ---------------------------------------------------------------------------
// fp16 transpose: in [R, Cc] -> out [Cc, R], per batch z
// ---------------------------------------------------------------------------
__global__ __launch_bounds__(256) void transpose_h(const __half* __restrict__ in,
                                                   __half* __restrict__ out,
                                                   int R, int Cc, long long sI, long long sO)
{
    __shared__ __half t[64][65];
    const __half* ip = in + (long long)blockIdx.z * sI;
    __half* op = out + (long long)blockIdx.z * sO;
    const int x0 = blockIdx.x * 64, y0 = blockIdx.y * 64;
    const int tid = threadIdx.x;
#pragma unroll
    for (int j = 0; j < 16; j++) {
        int idx = tid + 256 * j; int r = idx >> 6, cl = idx & 63;
        t[r][cl] = ip[(long long)(y0 + r) * Cc + x0 + cl];
    }
    __syncthreads();
#pragma unroll
    for (int j = 0; j < 16; j++) {
        int idx = tid + 256 * j; int r = idx >> 6, cl = idx & 63;
        op[(long long)(x0 + r) * R + y0 + cl] = t[cl][r];
    }
}

// fp32 -> fp16 elementwise (8 per thread)
__global__ void cvt_h(const float* __restrict__ in, __half* __restrict__ out, int n8)
{
    int i = blockIdx.x * blockDim.x + threadIdx.x;
    if (i < n8) {
        float4 a = ((const float4*)in)[2 * i];
        float4 b = ((const float4*)in)[2 * i + 1];
        __half2 h[4] = { __floats2half2_rn(a.x, a.y), __floats2half2_rn(a.z, a.w),
                         __floats2half2_rn(b.x, b.y), __floats2half2_rn(b.z, b.w) };
        ((uint4*)out)[i] = *(uint4*)h;
    }
}

// ---------------------------------------------------------------------------
extern "C" void kernel_launch(void* const* d_in, const int* in_sizes, int n_in,
                              void* d_out, int out_size)
{
    const int Bb = 8, NK = 2048, NQ = 2048, D = 256, H = 1024;
    const float scale = 1.0f / 32.0f;

    const float* KEY   = (const float*)d_in[0];
    const float* VALUE = (const float*)d_in[1];
    const float* QUERY = (const float*)d_in[2];
    const float* Wk_w  = (const float*)d_in[3];
    const float* Wk_b  = (const float*)d_in[4];
    const float* Wq_w  = (const float*)d_in[5];
    const float* Wq_b  = (const float*)d_in[6];
    const float* Wv_w  = (const float*)d_in[7];
    const float* Wv_b  = (const float*)d_in[8];
    const float* lin_w = (const float*)d_in[9];
    const float* lin_b = (const float*)d_in[10];
    float* out = (float*)d_out;

    __half *key, *val, *qry, *wkw, *wqw, *wvw, *linw, *Wk, *Wq, *Wv, *WvT, *w, *wT, *ctx;
    float* dist;
    cudaGetSymbolAddress((void**)&key, h_key);
    cudaGetSymbolAddress((void**)&val, h_val);
    cudaGetSymbolAddress((void**)&qry, h_qry);
    cudaGetSymbolAddress((void**)&wkw, h_wkw);
    cudaGetSymbolAddress((void**)&wqw, h_wqw);
    cudaGetSymbolAddress((void**)&wvw, h_wvw);
    cudaGetSymbolAddress((void**)&linw, h_linw);
    cudaGetSymbolAddress((void**)&Wk, h_Wk);
    cudaGetSymbolAddress((void**)&Wq, h_Wq);
    cudaGetSymbolAddress((void**)&Wv, h_Wv);
    cudaGetSymbolAddress((void**)&WvT, h_WvT);
    cudaGetSymbolAddress((void**)&dist, g_dist);
    cudaGetSymbolAddress((void**)&w, h_w);
    cudaGetSymbolAddress((void**)&wT, h_wT);
    cudaGetSymbolAddress((void**)&ctx, h_ctx);

    (void)cudaFuncSetAttribute(gemm_h<0>, cudaFuncAttributeMaxDynamicSharedMemorySize, SMEM_REQ);
    (void)cudaFuncSetAttribute(gemm_h<1>, cudaFuncAttributeMaxDynamicSharedMemorySize, SMEM_REQ);
    (void)cudaFuncSetAttribute(gemm_h<2>, cudaFuncAttributeMaxDynamicSharedMemorySize, SMEM_REQ);
    (void)cudaFuncSetAttribute(gemm_h<3>, cudaFuncAttributeMaxDynamicSharedMemorySize, SMEM_REQ);

    // fp16 conversions of inputs
    cvt_h<<<(Bb*NK*D/8 + 255)/256, 256>>>(KEY,   key,  Bb*NK*D/8);
    cvt_h<<<(Bb*NK*D/8 + 255)/256, 256>>>(VALUE, val,  Bb*NK*D/8);
    cvt_h<<<(Bb*NQ*D/8 + 255)/256, 256>>>(QUERY, qry,  Bb*NQ*D/8);
    cvt_h<<<(H*D/8 + 255)/256, 256>>>(Wk_w, wkw, H*D/8);
    cvt_h<<<(H*D/8 + 255)/256, 256>>>(Wq_w, wqw, H*D/8);
    cvt_h<<<(H*D/8 + 255)/256, 256>>>(Wv_w, wvw, H*D/8);
    cvt_h<<<(D*H/8 + 255)/256, 256>>>(lin_w, linw, D*H/8);

    dim3 thr(256);

    // Projections -> fp16 [B*N, H] (+bias)
    gemm_h<0><<<dim3(H/128, (Bb*NK)/128, 1), thr, SMEM_REQ>>>(
        key, wkw, Wk, Wk_b, Bb*NK, H, D, 1.f, 0, 0, 0);
    gemm_h<0><<<dim3(H/128, (Bb*NQ)/128, 1), thr, SMEM_REQ>>>(
        qry, wqw, Wq, Wq_b, Bb*NQ, H, D, 1.f, 0, 0, 0);
    gemm_h<0><<<dim3(H/128, (Bb*NK)/128, 1), thr, SMEM_REQ>>>(
        val, wvw, Wv, Wv_b, Bb*NK, H, D, 1.f, 0, 0, 0);

    // dist[b,i,k] (fp32, scaled)
    gemm_h<1><<<dim3(NQ/128, NK/128, Bb), thr, SMEM_REQ>>>(
        Wk, Wq, dist, nullptr, NK, NQ, H, scale,
        (long long)NK*H, (long long)NQ*H, (long long)NK*NQ);

    // softmax over k -> fp16 weights
    softmax_h<<<Bb*NK, 256>>>(dist, w);

    // transposes: w[i,k] -> wT[k,i]; Wv[i,h] -> WvT[h,i]
    transpose_h<<<dim3(NQ/64, NK/64, Bb), 256>>>(w, wT, NK, NQ,
        (long long)NK*NQ, (long long)NK*NQ);
    transpose_h<<<dim3(H/64, NK/64, Bb), 256>>>(Wv, WvT, NK, H,
        (long long)NK*H, (long long)NK*H);

    // context[b,k,h] = wT[k,:] . WvT[h,:]  -> fp16
    gemm_h<3><<<dim3(H/128, NQ/128, Bb), thr, SMEM_REQ>>>(
        wT, WvT, ctx, nullptr, NQ, H, NK, 1.f,
        (long long)NK*NQ, (long long)NK*H, (long long)NQ*H);

    // res = ctx @ lin_w^T + lin_b -> fp32 out
    gemm_h<2><<<dim3(D/128, (Bb*NQ)/128, 1), thr, SMEM_REQ>>>(
        ctx, linw, out, lin_b, Bb*NQ, D, H, 1.f, 0, 0, 0);
}

// round 8
// speedup vs baseline: 9.2476x; 1.3026x over previous
#include <cuda_runtime.h>
#include <cuda_fp16.h>
#include <cstdint>

// B=8, NK=NQ=2048, D=256, H=1024
// Folded algebra:
//   dist = scale*(KEY·G·QUERY^T + b_k)   (row-constants drop in softmax)
//   res  = w^T·(VALUE·P + q) + lin_b
// GEMM core: C[M,N] = A[M,K]·B[N,K]^T, fp16 ops (mma.m16n8k16), fp32 accum.

#define KC     64
#define NSTG   3
#define TILE_B 16384
#define STG_B  (2 * TILE_B)
#define SMEM_REQ (NSTG * STG_B)      // 98304 B

// ---------------- scratch ----------------------------------------------------
__device__ __half h_key [8u*2048u*256u];
__device__ __half h_val [8u*2048u*256u];
__device__ __half h_qry [8u*2048u*256u];
__device__ __half h_G2  [256u*256u];          // G2[e,d] = sum_h Wq[h,e]·Wk[h,d]
__device__ __half h_P2  [256u*256u];          // P2[o,d] = sum_h Wv[h,d]·lin[o,h]
__device__ float  g_v   [256];                // v[e] = sum_h bk[h]·Wq[h,e]
__device__ float  g_q   [256];                // q[o] = sum_h bv[h]·lin[o,h]
__device__ float  g_b   [8u*2048u];           // b[k] = sum_e Q[k,e]·v[e]
__device__ __half h_KG  [8u*2048u*256u];      // KEY·G
__device__ __half h_VP  [8u*2048u*256u];      // VALUE·P + q
__device__ __half h_VPT [8u*256u*2048u];
__device__ __half h_dist[(size_t)8*2048*2048];
__device__ __half h_w   [(size_t)8*2048*2048];
__device__ __half h_wT  [(size_t)8*2048*2048];

// ---------------- PTX helpers -----------------------------------------------
__device__ __forceinline__ uint32_t smem_u32(const void* p) {
    uint32_t a;
    asm("{ .reg .u64 t; cvta.to.shared.u64 t, %1; cvt.u32.u64 %0, t; }" : "=r"(a) : "l"(p));
    return a;
}
__device__ __forceinline__ void cp16s(uint32_t s, const void* g) {
    asm volatile("cp.async.cg.shared.global [%0], [%1], 16;" :: "r"(s), "l"(g));
}
#define CP_COMMIT() asm volatile("cp.async.commit_group;")
#define CP_WAIT(n)  asm volatile("cp.async.wait_group %0;" :: "n"(n))

__device__ __forceinline__ void ldsm4(uint32_t& r0, uint32_t& r1, uint32_t& r2, uint32_t& r3,
                                      uint32_t addr) {
    asm volatile("ldmatrix.sync.aligned.m8n8.x4.shared.b16 {%0,%1,%2,%3}, [%4];"
                 : "=r"(r0), "=r"(r1), "=r"(r2), "=r"(r3) : "r"(addr));
}
#define MMA_F16(c, a, b)                                                       \
    asm volatile(                                                              \
        "mma.sync.aligned.m16n8k16.row.col.f32.f16.f16.f32 "                   \
        "{%0,%1,%2,%3},{%4,%5,%6,%7},{%8,%9},{%0,%1,%2,%3};"                   \
        : "+f"(c[0]), "+f"(c[1]), "+f"(c[2]), "+f"(c[3])                       \
        : "r"(a[0]), "r"(a[1]), "r"(a[2]), "r"(a[3]), "r"(b[0]), "r"(b[1]))

// ---------------------------------------------------------------------------
// fp16 NT GEMM: tile 128x128, BK=64, 3-stage cp.async, 8 warps @ 64x32.
// EPI: 0 = +bias[n] -> half      (VP with q)
//      1 = (x+bias[n])*scale -> half   (dist with b_k)
//      2 = +bias[n] -> float     (res with lin_b)
//      3 = plain -> half         (KG)
// ---------------------------------------------------------------------------
template <int EPI>
__global__ __launch_bounds__(256, 2) void gemm_h(
    const __half* __restrict__ Ag, const __half* __restrict__ Bg,
    void* __restrict__ Cg, const float* __restrict__ biasg,
    int M, int N, int K, float scale,
    long long sA, long long sB, long long sC, long long sBias)
{
    extern __shared__ char smem_raw[];
    const uint32_t sb = smem_u32(smem_raw);

    const int tid = threadIdx.x, lane = tid & 31, w = tid >> 5;
    const int wm = (w & 1) * 64;
    const int wn = (w >> 1) * 32;
    const __half* A  = Ag + (long long)blockIdx.z * sA;
    const __half* Bm = Bg + (long long)blockIdx.z * sB;
    const float* bias = biasg + (biasg ? (long long)blockIdx.z * sBias : 0);
    const long long cb = (long long)blockIdx.z * sC;
    const int m0 = blockIdx.y * 128, n0 = blockIdx.x * 128;

    float acc[4][4][4];
#pragma unroll
    for (int mt = 0; mt < 4; mt++)
#pragma unroll
        for (int nt = 0; nt < 4; nt++)
#pragma unroll
            for (int r = 0; r < 4; r++) acc[mt][nt][r] = 0.f;

    const int laneRowA = lane & 15;
    const int granA    = lane >> 4;
    const int swA      = laneRowA & 7;
    const int laneRowB = ((lane >> 4) << 3) + (lane & 7);
    const int granB    = (lane >> 3) & 1;
    const int swB      = lane & 7;

    auto load_chunk = [&](int c) {
        const int st = c % NSTG;
        const uint32_t sa  = sb + st * STG_B;
        const uint32_t sbu = sa + TILE_B;
        const char* ap = (const char*)A  + ((long long)m0 * K + (long long)c * KC) * 2;
        const char* bp = (const char*)Bm + ((long long)n0 * K + (long long)c * KC) * 2;
#pragma unroll
        for (int j = 0; j < 4; j++) {
            int gi = tid + 256 * j;
            int r = gi >> 3, g = gi & 7;
            uint32_t sw = (uint32_t)((g ^ (r & 7)) << 4) + (uint32_t)(r << 7);
            cp16s(sa  + sw, ap + (long long)r * K * 2 + g * 16);
            cp16s(sbu + sw, bp + (long long)r * K * 2 + g * 16);
        }
        CP_COMMIT();
    };

    const int C = K / KC;
    load_chunk(0); load_chunk(1);

    for (int c = 0; c < C; c++) {
        if (c + 2 < C) load_chunk(c + 2);

        if (c + 2 < C)      { CP_WAIT(2); }
        else if (c + 1 < C) { CP_WAIT(1); }
        else                { CP_WAIT(0); }
        __syncthreads();

        const uint32_t sa  = sb + (c % NSTG) * STG_B;
        const uint32_t sbu = sa + TILE_B;

#pragma unroll
        for (int ks = 0; ks < 4; ks++) {
            uint32_t bf[4][2];
#pragma unroll
            for (int np = 0; np < 2; np++) {
                int rB = wn + np * 16 + laneRowB;
                uint32_t addr = sbu + (uint32_t)(rB << 7)
                              + (uint32_t)((((ks << 1) + granB) ^ swB) << 4);
                ldsm4(bf[2 * np][0], bf[2 * np][1], bf[2 * np + 1][0], bf[2 * np + 1][1], addr);
            }
#pragma unroll
            for (int mt = 0; mt < 4; mt++) {
                int rA = wm + mt * 16 + laneRowA;
                uint32_t addr = sa + (uint32_t)(rA << 7)
                              + (uint32_t)((((ks << 1) + granA) ^ swA) << 4);
                uint32_t af[4];
                ldsm4(af[0], af[1], af[2], af[3], addr);
#pragma unroll
                for (int nt = 0; nt < 4; nt++)
                    MMA_F16(acc[mt][nt], af, bf[nt]);
            }
        }
        __syncthreads();
    }

    const int gr = lane >> 2, t4 = lane & 3;
#pragma unroll
    for (int mt = 0; mt < 4; mt++) {
        int r = m0 + wm + mt * 16 + gr;
#pragma unroll
        for (int nt = 0; nt < 4; nt++) {
            int cidx = n0 + wn + nt * 8 + 2 * t4;
            float x0 = acc[mt][nt][0], x1 = acc[mt][nt][1];
            float x2 = acc[mt][nt][2], x3 = acc[mt][nt][3];
            if (EPI == 0 || EPI == 1 || EPI == 2) {
                float b0 = bias[cidx], b1 = bias[cidx + 1];
                x0 += b0; x1 += b1; x2 += b0; x3 += b1;
            }
            if (EPI == 1) { x0 *= scale; x1 *= scale; x2 *= scale; x3 *= scale; }
            if (EPI == 2) {
                float* Co = (float*)Cg + cb;
                *(float2*)(Co + (long long)r * N + cidx) = make_float2(x0, x1);
                *(float2*)(Co + (long long)(r + 8) * N + cidx) = make_float2(x2, x3);
            } else {
                __half* Co = (__half*)Cg + cb;
                *(__half2*)(Co + (long long)r * N + cidx) = __floats2half2_rn(x0, x1);
                *(__half2*)(Co + (long long)(r + 8) * N + cidx) = __floats2half2_rn(x2, x3);
            }
        }
    }
}

// ---------------------------------------------------------------------------
// Small fp32 GEMM (256x256 out, K=1024) -> fp16.
// TRANSA=1: C[e,d] = sum_h A[h,e]·B[h,d]   (A,B: [1024,256])
// TRANSA=0: C[o,d] = sum_h A[o,h]·B[h,d]   (A: [256,1024], B: [1024,256])
// ---------------------------------------------------------------------------
template <int TRANSA>
__global__ __launch_bounds__(256) void small_gemm(
    const float* __restrict__ A, const float* __restrict__ B, __half* __restrict__ Cc)
{
    __shared__ float sA[64][65], sB[64][65];
    const int e0 = blockIdx.x * 64, d0 = blockIdx.y * 64;
    const int tid = threadIdx.x, tx = tid & 15, ty = tid >> 4;

    float acc[4][4];
#pragma unroll
    for (int i = 0; i < 4; i++)
#pragma unroll
        for (int j = 0; j < 4; j++) acc[i][j] = 0.f;

    for (int h0 = 0; h0 < 1024; h0 += 64) {
#pragma unroll
        for (int j = 0; j < 16; j++) {
            int li = tid + 256 * j;
            int r = li >> 6, cl = li & 63;
            if (TRANSA) sA[r][cl] = A[(h0 + r) * 256 + e0 + cl];       // sA[h][e]
            else        sA[cl][r] = A[(e0 + r) * 1024 + h0 + cl];      // sA[h][o]
            sB[r][cl] = B[(h0 + r) * 256 + d0 + cl];                   // sB[h][d]
        }
        __syncthreads();
#pragma unroll
        for (int h = 0; h < 64; h++) {
            float a[4], b[4];
#pragma unroll
            for (int i = 0; i < 4; i++) a[i] = sA[h][ty * 4 + i];
#pragma unroll
            for (int j = 0; j < 4; j++) b[j] = sB[h][tx * 4 + j];
#pragma unroll
            for (int i = 0; i < 4; i++)
#pragma unroll
                for (int j = 0; j < 4; j++) acc[i][j] += a[i] * b[j];
        }
        __syncthreads();
    }
#pragma unroll
    for (int i = 0; i < 4; i++)
#pragma unroll
        for (int j = 0; j < 4; j++)
            Cc[(e0 + ty * 4 + i) * 256 + d0 + tx * 4 + j] = __float2half_rn(acc[i][j]);
}

// v[e] = sum_h vec[h]·W[h*256+e]   (1 block, 256 threads)
__global__ void vecmat_col(const float* __restrict__ vec, const float* __restrict__ W,
                           float* __restrict__ o)
{
    int e = threadIdx.x;
    float acc = 0.f;
#pragma unroll 8
    for (int h = 0; h < 1024; h++) acc += vec[h] * W[h * 256 + e];
    o[e] = acc;
}

// q[o] = sum_h vec[h]·W[o*1024+h]  (grid 256 blocks x 32 threads)
__global__ void vecmat_row(const float* __restrict__ vec, const float* __restrict__ W,
                           float* __restrict__ o)
{
    int ob = blockIdx.x, lane = threadIdx.x;
    float acc = 0.f;
    for (int h = lane; h < 1024; h += 32) acc += vec[h] * W[ob * 1024 + h];
#pragma unroll
    for (int of = 16; of > 0; of >>= 1) acc += __shfl_xor_sync(0xffffffffu, acc, of);
    if (lane == 0) o[ob] = acc;
}

// b[k] = sum_e Q[k*256+e]·v[e]
__global__ __launch_bounds__(256) void bvec(const __half* __restrict__ Q,
                                            const float* __restrict__ v,
                                            float* __restrict__ ob)
{
    __shared__ float sv[256];
    sv[threadIdx.x] = v[threadIdx.x];
    __syncthreads();
    int k = blockIdx.x * 256 + threadIdx.x;
    const __half* row = Q + (long long)k * 256;
    float acc = 0.f;
#pragma unroll 16
    for (int e = 0; e < 256; e += 2) {
        __half2 h2 = *(const __half2*)(row + e);
        acc += __low2float(h2) * sv[e] + __high2float(h2) * sv[e + 1];
    }
    ob[k] = acc;
}

// ---------------------------------------------------------------------------
// Row softmax over 2048 fp16 logits -> fp16 weights
// ---------------------------------------------------------------------------
__global__ __launch_bounds__(256) void softmax_h(const __half* __restrict__ d,
                                                 __half* __restrict__ o)
{
    long long row = blockIdx.x;
    const __half* p = d + row * 2048ll;
    __half* q = o + row * 2048ll;
    int t = threadIdx.x;

    float v[8];
    float m = -1e30f;
#pragma unroll
    for (int j = 0; j < 8; j++) { v[j] = __half2float(p[t + (j << 8)]); m = fmaxf(m, v[j]); }
#pragma unroll
    for (int of = 16; of > 0; of >>= 1) m = fmaxf(m, __shfl_xor_sync(0xffffffffu, m, of));
    __shared__ float redm[8];
    if ((t & 31) == 0) redm[t >> 5] = m;
    __syncthreads();
#pragma unroll
    for (int w2 = 0; w2 < 8; w2++) m = fmaxf(m, redm[w2]);

    float s = 0.f;
#pragma unroll
    for (int j = 0; j < 8; j++) { v[j] = __expf(v[j] - m); s += v[j]; }
#pragma unroll
    for (int of = 16; of > 0; of >>= 1) s += __shfl_xor_sync(0xffffffffu, s, of);
    __shared__ float reds[8];
    if ((t & 31) == 0) reds[t >> 5] = s;
    __syncthreads();
    s = 0.f;
#pragma unroll
    for (int w2 = 0; w2 < 8; w2++) s += reds[w2];
    float inv = 1.f / s;
#pragma unroll
    for (int j = 0; j < 8; j++) q[t + (j << 8)] = __float2half_rn(v[j] * inv);
}

// ---------------------------------------------------------------------------
// fp16 transpose: in [rows, Cc] -> out [Cc, rows], per batch z
// grid: (Cc/64, rows/64, batches)
// ---------------------------------------------------------------------------
__global__ __launch_bounds__(256) void transpose_h(const __half* __restrict__ in,
                                                   __half* __restrict__ out,
                                                   int R, int Cc, long long sI, long long sO)
{
    __shared__ __half t[64][65];
    const __half* ip = in + (long long)blockIdx.z * sI;
    __half* op = out + (long long)blockIdx.z * sO;
    const int x0 = blockIdx.x * 64, y0 = blockIdx.y * 64;
    const int tid = threadIdx.x;
#pragma unroll
    for (int j = 0; j < 16; j++) {
        int idx = tid + 256 * j; int r = idx >> 6, cl = idx & 63;
        t[r][cl] = ip[(long long)(y0 + r) * Cc + x0 + cl];
    }
    __syncthreads();
#pragma unroll
    for (int j = 0; j < 16; j++) {
        int idx = tid + 256 * j; int r = idx >> 6, cl = idx & 63;
        op[(long long)(x0 + r) * R + y0 + cl] = t[cl][r];
    }
}

// fp32 -> fp16 elementwise (8 per thread)
__global__ void cvt_h(const float* __restrict__ in, __half* __restrict__ out, int n8)
{
    int i = blockIdx.x * blockDim.x + threadIdx.x;
    if (i < n8) {
        float4 a = ((const float4*)in)[2 * i];
        float4 b = ((const float4*)in)[2 * i + 1];
        __half2 h[4] = { __floats2half2_rn(a.x, a.y), __floats2half2_rn(a.z, a.w),
                         __floats2half2_rn(b.x, b.y), __floats2half2_rn(b.z, b.w) };
        ((uint4*)out)[i] = *(uint4*)h;
    }
}

// ---------------------------------------------------------------------------
extern "C" void kernel_launch(void* const* d_in, const int* in_sizes, int n_in,
                              void* d_out, int out_size)
{
    const int Bb = 8, NK = 2048, NQ = 2048, D = 256, H = 1024;
    const float scale = 1.0f / 32.0f;

    const float* KEY   = (const float*)d_in[0];
    const float* VALUE = (const float*)d_in[1];
    const float* QUERY = (const float*)d_in[2];
    const float* Wk_w  = (const float*)d_in[3];
    const float* Wk_b  = (const float*)d_in[4];
    const float* Wq_w  = (const float*)d_in[5];
    const float* Wq_b  = (const float*)d_in[6];
    const float* Wv_w  = (const float*)d_in[7];
    const float* Wv_b  = (const float*)d_in[8];
    const float* lin_w = (const float*)d_in[9];
    const float* lin_b = (const float*)d_in[10];
    float* out = (float*)d_out;
    (void)Wq_b;  // enters only via row-constant terms that cancel in softmax

    __half *key, *val, *qry, *G2, *P2, *KG, *VP, *VPT, *dist, *w, *wT;
    float *vv, *qq, *bb;
    cudaGetSymbolAddress((void**)&key, h_key);
    cudaGetSymbolAddress((void**)&val, h_val);
    cudaGetSymbolAddress((void**)&qry, h_qry);
    cudaGetSymbolAddress((void**)&G2, h_G2);
    cudaGetSymbolAddress((void**)&P2, h_P2);
    cudaGetSymbolAddress((void**)&vv, g_v);
    cudaGetSymbolAddress((void**)&qq, g_q);
    cudaGetSymbolAddress((void**)&bb, g_b);
    cudaGetSymbolAddress((void**)&KG, h_KG);
    cudaGetSymbolAddress((void**)&VP, h_VP);
    cudaGetSymbolAddress((void**)&VPT, h_VPT);
    cudaGetSymbolAddress((void**)&dist, h_dist);
    cudaGetSymbolAddress((void**)&w, h_w);
    cudaGetSymbolAddress((void**)&wT, h_wT);

    (void)cudaFuncSetAttribute(gemm_h<0>, cudaFuncAttributeMaxDynamicSharedMemorySize, SMEM_REQ);
    (void)cudaFuncSetAttribute(gemm_h<1>, cudaFuncAttributeMaxDynamicSharedMemorySize, SMEM_REQ);
    (void)cudaFuncSetAttribute(gemm_h<2>, cudaFuncAttributeMaxDynamicSharedMemorySize, SMEM_REQ);
    (void)cudaFuncSetAttribute(gemm_h<3>, cudaFuncAttributeMaxDynamicSharedMemorySize, SMEM_REQ);

    // fp16 copies of the big inputs
    cvt_h<<<(Bb*NK*D/8 + 255)/256, 256>>>(KEY,   key, Bb*NK*D/8);
    cvt_h<<<(Bb*NK*D/8 + 255)/256, 256>>>(VALUE, val, Bb*NK*D/8);
    cvt_h<<<(Bb*NQ*D/8 + 255)/256, 256>>>(QUERY, qry, Bb*NQ*D/8);

    // Folded weight products
    small_gemm<1><<<dim3(4,4), 256>>>(Wq_w, Wk_w, G2);   // G2[e,d]
    small_gemm<0><<<dim3(4,4), 256>>>(lin_w, Wv_w, P2);  // P2[o,d]
    vecmat_col<<<1, 256>>>(Wk_b, Wq_w, vv);              // v[e]
    vecmat_row<<<256, 32>>>(Wv_b, lin_w, qq);            // q[o]
    bvec<<<Bb*NQ/256, 256>>>(qry, vv, bb);               // b[k]

    dim3 thr(256);

    // KG = KEYh · G2^T  -> fp16 [B*NK, 256]
    gemm_h<3><<<dim3(2, 128, 1), thr, SMEM_REQ>>>(
        key, G2, KG, nullptr, Bb*NK, 256, 256, 1.f, 0, 0, 0, 0);

    // VP = VALUEh · P2^T + q -> fp16 [B*NK, 256]
    gemm_h<0><<<dim3(2, 128, 1), thr, SMEM_REQ>>>(
        val, P2, VP, qq, Bb*NK, 256, 256, 1.f, 0, 0, 0, 0);

    // dist[b,i,k] = scale*(KG·Q^T + b[k]) -> fp16, batched
    gemm_h<1><<<dim3(16, 16, Bb), thr, SMEM_REQ>>>(
        KG, qry, dist, bb, NK, NQ, 256, scale,
        (long long)NK*256, (long long)NQ*256, (long long)NK*NQ, NQ);

    // softmax over k -> fp16 w
    softmax_h<<<Bb*NK, 256>>>(dist, w);

    // w[i,k] -> wT[k,i]
    transpose_h<<<dim3(NQ/64, NK/64, Bb), 256>>>(w, wT, NK, NQ,
        (long long)NK*NQ, (long long)NK*NQ);

    // VP[i,o] -> VPT[o,i] per batch
    transpose_h<<<dim3(256/64, NK/64, Bb), 256>>>(VP, VPT, NK, 256,
        (long long)NK*256, (long long)NK*256);

    // res[b,k,o] = wT·VPT^T + lin_b -> fp32 out
    gemm_h<2><<<dim3(2, 16, Bb), thr, SMEM_REQ>>>(
        wT, VPT, out, lin_b, NQ, 256, NK, 1.f,
        (long long)NK*NQ, (long long)NK*256, (long long)NQ*256, 0);
}

// round 9
// speedup vs baseline: 12.8263x; 1.3870x over previous
#include <cuda_runtime.h>
#include <cuda_fp16.h>
#include <cstdint>

// B=8, NK=NQ=2048, D=256, H=1024
// Folded algebra:
//   dist = scale*(KEY·G·QUERY^T + b_k)   (row-constants drop in softmax)
//   res  = w^T·(VALUE·P + q) + lin_b
// GEMM core: C[M,N] = A[M,K]·B[N,K]^T, fp16 ops (mma.m16n8k16), fp32 accum.

#define KC     64
#define NSTG   3
#define TILE_B 16384
#define STG_B  (2 * TILE_B)
#define SMEM_REQ (NSTG * STG_B)      // 98304 B

// ---------------- scratch ----------------------------------------------------
__device__ __half h_key [8u*2048u*256u];
__device__ __half h_val [8u*2048u*256u];
__device__ __half h_qry [8u*2048u*256u];
__device__ float  g_G2f [256u*256u];          // fp32 split-K accumulator
__device__ float  g_P2f [256u*256u];
__device__ __half h_G2  [256u*256u];          // G2[e,d] = sum_h Wq[h,e]·Wk[h,d]
__device__ __half h_P2  [256u*256u];          // P2[o,d] = sum_h Wv[h,d]·lin[o,h]
__device__ float  g_v   [256];                // v[e] = sum_h bk[h]·Wq[h,e]
__device__ float  g_q   [256];                // q[o] = sum_h bv[h]·lin[o,h]
__device__ float  g_b   [8u*2048u];           // b[k] = sum_e Q[k,e]·v[e]
__device__ __half h_KG  [8u*2048u*256u];      // KEY·G
__device__ __half h_VP  [8u*2048u*256u];      // VALUE·P + q
__device__ __half h_VPT [8u*256u*2048u];
__device__ __half h_dist[(size_t)8*2048*2048];
__device__ __half h_w   [(size_t)8*2048*2048];
__device__ __half h_wT  [(size_t)8*2048*2048];

// ---------------- PTX helpers -----------------------------------------------
__device__ __forceinline__ uint32_t smem_u32(const void* p) {
    uint32_t a;
    asm("{ .reg .u64 t; cvta.to.shared.u64 t, %1; cvt.u32.u64 %0, t; }" : "=r"(a) : "l"(p));
    return a;
}
__device__ __forceinline__ void cp16s(uint32_t s, const void* g) {
    asm volatile("cp.async.cg.shared.global [%0], [%1], 16;" :: "r"(s), "l"(g));
}
#define CP_COMMIT() asm volatile("cp.async.commit_group;")
#define CP_WAIT(n)  asm volatile("cp.async.wait_group %0;" :: "n"(n))

__device__ __forceinline__ void ldsm4(uint32_t& r0, uint32_t& r1, uint32_t& r2, uint32_t& r3,
                                      uint32_t addr) {
    asm volatile("ldmatrix.sync.aligned.m8n8.x4.shared.b16 {%0,%1,%2,%3}, [%4];"
                 : "=r"(r0), "=r"(r1), "=r"(r2), "=r"(r3) : "r"(addr));
}
#define MMA_F16(c, a, b)                                                       \
    asm volatile(                                                              \
        "mma.sync.aligned.m16n8k16.row.col.f32.f16.f16.f32 "                   \
        "{%0,%1,%2,%3},{%4,%5,%6,%7},{%8,%9},{%0,%1,%2,%3};"                   \
        : "+f"(c[0]), "+f"(c[1]), "+f"(c[2]), "+f"(c[3])                       \
        : "r"(a[0]), "r"(a[1]), "r"(a[2]), "r"(a[3]), "r"(b[0]), "r"(b[1]))

// ---------------------------------------------------------------------------
// fp16 NT GEMM: tile 128x128, BK=64, 3-stage cp.async, 8 warps @ 64x32.
// EPI: 0 = +bias[n] -> half          (VP with q)
//      1 = (x+bias[n])*scale -> half (dist with b_k)
//      2 = +bias[n] -> float         (res with lin_b)
//      3 = plain -> half             (KG)
// ---------------------------------------------------------------------------
template <int EPI>
__global__ __launch_bounds__(256, 2) void gemm_h(
    const __half* __restrict__ Ag, const __half* __restrict__ Bg,
    void* __restrict__ Cg, const float* __restrict__ biasg,
    int M, int N, int K, float scale,
    long long sA, long long sB, long long sC, long long sBias)
{
    extern __shared__ char smem_raw[];
    const uint32_t sb = smem_u32(smem_raw);

    const int tid = threadIdx.x, lane = tid & 31, w = tid >> 5;
    const int wm = (w & 1) * 64;
    const int wn = (w >> 1) * 32;
    const __half* A  = Ag + (long long)blockIdx.z * sA;
    const __half* Bm = Bg + (long long)blockIdx.z * sB;
    const float* bias = biasg + (biasg ? (long long)blockIdx.z * sBias : 0);
    const long long cb = (long long)blockIdx.z * sC;
    const int m0 = blockIdx.y * 128, n0 = blockIdx.x * 128;

    float acc[4][4][4];
#pragma unroll
    for (int mt = 0; mt < 4; mt++)
#pragma unroll
        for (int nt = 0; nt < 4; nt++)
#pragma unroll
            for (int r = 0; r < 4; r++) acc[mt][nt][r] = 0.f;

    const int laneRowA = lane & 15;
    const int granA    = lane >> 4;
    const int swA      = laneRowA & 7;
    const int laneRowB = ((lane >> 4) << 3) + (lane & 7);
    const int granB    = (lane >> 3) & 1;
    const int swB      = lane & 7;

    auto load_chunk = [&](int c) {
        const int st = c % NSTG;
        const uint32_t sa  = sb + st * STG_B;
        const uint32_t sbu = sa + TILE_B;
        const char* ap = (const char*)A  + ((long long)m0 * K + (long long)c * KC) * 2;
        const char* bp = (const char*)Bm + ((long long)n0 * K + (long long)c * KC) * 2;
#pragma unroll
        for (int j = 0; j < 4; j++) {
            int gi = tid + 256 * j;
            int r = gi >> 3, g = gi & 7;
            uint32_t sw = (uint32_t)((g ^ (r & 7)) << 4) + (uint32_t)(r << 7);
            cp16s(sa  + sw, ap + (long long)r * K * 2 + g * 16);
            cp16s(sbu + sw, bp + (long long)r * K * 2 + g * 16);
        }
        CP_COMMIT();
    };

    const int C = K / KC;
    load_chunk(0); load_chunk(1);

    for (int c = 0; c < C; c++) {
        if (c + 2 < C) load_chunk(c + 2);

        if (c + 2 < C)      { CP_WAIT(2); }
        else if (c + 1 < C) { CP_WAIT(1); }
        else                { CP_WAIT(0); }
        __syncthreads();

        const uint32_t sa  = sb + (c % NSTG) * STG_B;
        const uint32_t sbu = sa + TILE_B;

#pragma unroll
        for (int ks = 0; ks < 4; ks++) {
            uint32_t bf[4][2];
#pragma unroll
            for (int np = 0; np < 2; np++) {
                int rB = wn + np * 16 + laneRowB;
                uint32_t addr = sbu + (uint32_t)(rB << 7)
                              + (uint32_t)((((ks << 1) + granB) ^ swB) << 4);
                ldsm4(bf[2 * np][0], bf[2 * np][1], bf[2 * np + 1][0], bf[2 * np + 1][1], addr);
            }
#pragma unroll
            for (int mt = 0; mt < 4; mt++) {
                int rA = wm + mt * 16 + laneRowA;
                uint32_t addr = sa + (uint32_t)(rA << 7)
                              + (uint32_t)((((ks << 1) + granA) ^ swA) << 4);
                uint32_t af[4];
                ldsm4(af[0], af[1], af[2], af[3], addr);
#pragma unroll
                for (int nt = 0; nt < 4; nt++)
                    MMA_F16(acc[mt][nt], af, bf[nt]);
            }
        }
        __syncthreads();
    }

    const int gr = lane >> 2, t4 = lane & 3;
#pragma unroll
    for (int mt = 0; mt < 4; mt++) {
        int r = m0 + wm + mt * 16 + gr;
#pragma unroll
        for (int nt = 0; nt < 4; nt++) {
            int cidx = n0 + wn + nt * 8 + 2 * t4;
            float x0 = acc[mt][nt][0], x1 = acc[mt][nt][1];
            float x2 = acc[mt][nt][2], x3 = acc[mt][nt][3];
            if (EPI == 0 || EPI == 1 || EPI == 2) {
                float b0 = bias[cidx], b1 = bias[cidx + 1];
                x0 += b0; x1 += b1; x2 += b0; x3 += b1;
            }
            if (EPI == 1) { x0 *= scale; x1 *= scale; x2 *= scale; x3 *= scale; }
            if (EPI == 2) {
                float* Co = (float*)Cg + cb;
                *(float2*)(Co + (long long)r * N + cidx) = make_float2(x0, x1);
                *(float2*)(Co + (long long)(r + 8) * N + cidx) = make_float2(x2, x3);
            } else {
                __half* Co = (__half*)Cg + cb;
                *(__half2*)(Co + (long long)r * N + cidx) = __floats2half2_rn(x0, x1);
                *(__half2*)(Co + (long long)(r + 8) * N + cidx) = __floats2half2_rn(x2, x3);
            }
        }
    }
}

// ---------------------------------------------------------------------------
// Split-K small GEMM (256x256 out, K=1024), fp32, atomicAdd partials.
// grid (8,8,16): 32x32 output tile, K-chunk 64.
// TRANSA=1: C[e,d] += sum_h A[h,e]·B[h,d]   (A,B: [1024,256])
// TRANSA=0: C[o,d] += sum_h A[o,h]·B[h,d]   (A: [256,1024], B: [1024,256])
// ---------------------------------------------------------------------------
template <int TRANSA>
__global__ __launch_bounds__(256) void small_gemm_splitk(
    const float* __restrict__ A, const float* __restrict__ B, float* __restrict__ Cf)
{
    __shared__ float sA[64][33], sB[64][33];
    const int e0 = blockIdx.x * 32, d0 = blockIdx.y * 32, h0 = blockIdx.z * 64;
    const int tid = threadIdx.x;

#pragma unroll
    for (int j = 0; j < 8; j++) {
        int li = tid + 256 * j;                 // 0..2047
        if (TRANSA) {
            int r = li >> 5, cl = li & 31;      // coalesced over e
            sA[r][cl] = A[(h0 + r) * 256 + e0 + cl];
        } else {
            int cl = li >> 6, r = li & 63;      // coalesced over h
            sA[r][cl] = A[(e0 + cl) * 1024 + h0 + r];
        }
        int r = li >> 5, cl = li & 31;
        sB[r][cl] = B[(h0 + r) * 256 + d0 + cl];
    }
    __syncthreads();

    const int tx = tid & 15, ty = tid >> 4;     // tx: d (2 each), ty: e (2 each)
    float acc[2][2] = {{0.f, 0.f}, {0.f, 0.f}};
#pragma unroll
    for (int h = 0; h < 64; h++) {
        float a0 = sA[h][ty * 2], a1 = sA[h][ty * 2 + 1];
        float b0 = sB[h][tx * 2], b1 = sB[h][tx * 2 + 1];
        acc[0][0] += a0 * b0; acc[0][1] += a0 * b1;
        acc[1][0] += a1 * b0; acc[1][1] += a1 * b1;
    }
#pragma unroll
    for (int i = 0; i < 2; i++)
#pragma unroll
        for (int j = 0; j < 2; j++)
            atomicAdd(&Cf[(e0 + ty * 2 + i) * 256 + d0 + tx * 2 + j], acc[i][j]);
}

// fp32 -> fp16 elementwise (8 per thread)
__global__ void cvt_h(const float* __restrict__ in, __half* __restrict__ out, int n8)
{
    int i = blockIdx.x * blockDim.x + threadIdx.x;
    if (i < n8) {
        float4 a = ((const float4*)in)[2 * i];
        float4 b = ((const float4*)in)[2 * i + 1];
        __half2 h[4] = { __floats2half2_rn(a.x, a.y), __floats2half2_rn(a.z, a.w),
                         __floats2half2_rn(b.x, b.y), __floats2half2_rn(b.z, b.w) };
        ((uint4*)out)[i] = *(uint4*)h;
    }
}

// v[e] = sum_h vec[h]·W[h*256+e]   (1 block, 256 threads)
__global__ void vecmat_col(const float* __restrict__ vec, const float* __restrict__ W,
                           float* __restrict__ o)
{
    int e = threadIdx.x;
    float acc = 0.f;
#pragma unroll 8
    for (int h = 0; h < 1024; h++) acc += vec[h] * W[h * 256 + e];
    o[e] = acc;
}

// q[o] = sum_h vec[h]·W[o*1024+h]  (grid 256 blocks x 32 threads)
__global__ void vecmat_row(const float* __restrict__ vec, const float* __restrict__ W,
                           float* __restrict__ o)
{
    int ob = blockIdx.x, lane = threadIdx.x;
    float acc = 0.f;
    for (int h = lane; h < 1024; h += 32) acc += vec[h] * W[ob * 1024 + h];
#pragma unroll
    for (int of = 16; of > 0; of >>= 1) acc += __shfl_xor_sync(0xffffffffu, acc, of);
    if (lane == 0) o[ob] = acc;
}

// b[k] = sum_e Q[k*256+e]·v[e]
__global__ __launch_bounds__(256) void bvec(const __half* __restrict__ Q,
                                            const float* __restrict__ v,
                                            float* __restrict__ ob)
{
    __shared__ float sv[256];
    sv[threadIdx.x] = v[threadIdx.x];
    __syncthreads();
    int k = blockIdx.x * 256 + threadIdx.x;
    const __half* row = Q + (long long)k * 256;
    float acc = 0.f;
#pragma unroll 16
    for (int e = 0; e < 256; e += 2) {
        __half2 h2 = *(const __half2*)(row + e);
        acc += __low2float(h2) * sv[e] + __high2float(h2) * sv[e + 1];
    }
    ob[k] = acc;
}

// ---------------------------------------------------------------------------
// Row softmax over 2048 fp16 logits -> fp16 weights
// ---------------------------------------------------------------------------
__global__ __launch_bounds__(256) void softmax_h(const __half* __restrict__ d,
                                                 __half* __restrict__ o)
{
    long long row = blockIdx.x;
    const __half* p = d + row * 2048ll;
    __half* q = o + row * 2048ll;
    int t = threadIdx.x;

    float v[8];
    float m = -1e30f;
#pragma unroll
    for (int j = 0; j < 8; j++) { v[j] = __half2float(p[t + (j << 8)]); m = fmaxf(m, v[j]); }
#pragma unroll
    for (int of = 16; of > 0; of >>= 1) m = fmaxf(m, __shfl_xor_sync(0xffffffffu, m, of));
    __shared__ float redm[8];
    if ((t & 31) == 0) redm[t >> 5] = m;
    __syncthreads();
#pragma unroll
    for (int w2 = 0; w2 < 8; w2++) m = fmaxf(m, redm[w2]);

    float s = 0.f;
#pragma unroll
    for (int j = 0; j < 8; j++) { v[j] = __expf(v[j] - m); s += v[j]; }
#pragma unroll
    for (int of = 16; of > 0; of >>= 1) s += __shfl_xor_sync(0xffffffffu, s, of);
    __shared__ float reds[8];
    if ((t & 31) == 0) reds[t >> 5] = s;
    __syncthreads();
    s = 0.f;
#pragma unroll
    for (int w2 = 0; w2 < 8; w2++) s += reds[w2];
    float inv = 1.f / s;
#pragma unroll
    for (int j = 0; j < 8; j++) q[t + (j << 8)] = __float2half_rn(v[j] * inv);
}

// ---------------------------------------------------------------------------
// fp16 transpose: in [rows, Cc] -> out [Cc, rows], per batch z
// grid: (Cc/64, rows/64, batches)
// ---------------------------------------------------------------------------
__global__ __launch_bounds__(256) void transpose_h(const __half* __restrict__ in,
                                                   __half* __restrict__ out,
                                                   int R, int Cc, long long sI, long long sO)
{
    __shared__ __half t[64][65];
    const __half* ip = in + (long long)blockIdx.z * sI;
    __half* op = out + (long long)blockIdx.z * sO;
    const int x0 = blockIdx.x * 64, y0 = blockIdx.y * 64;
    const int tid = threadIdx.x;
#pragma unroll
    for (int j = 0; j < 16; j++) {
        int idx = tid + 256 * j; int r = idx >> 6, cl = idx & 63;
        t[r][cl] = ip[(long long)(y0 + r) * Cc + x0 + cl];
    }
    __syncthreads();
#pragma unroll
    for (int j = 0; j < 16; j++) {
        int idx = tid + 256 * j; int r = idx >> 6, cl = idx & 63;
        op[(long long)(x0 + r) * R + y0 + cl] = t[cl][r];
    }
}

// ---------------------------------------------------------------------------
extern "C" void kernel_launch(void* const* d_in, const int* in_sizes, int n_in,
                              void* d_out, int out_size)
{
    const int Bb = 8, NK = 2048, NQ = 2048, D = 256, H = 1024;
    const float scale = 1.0f / 32.0f;

    const float* KEY   = (const float*)d_in[0];
    const float* VALUE = (const float*)d_in[1];
    const float* QUERY = (const float*)d_in[2];
    const float* Wk_w  = (const float*)d_in[3];
    const float* Wk_b  = (const float*)d_in[4];
    const float* Wq_w  = (const float*)d_in[5];
    const float* Wq_b  = (const float*)d_in[6];
    const float* Wv_w  = (const float*)d_in[7];
    const float* Wv_b  = (const float*)d_in[8];
    const float* lin_w = (const float*)d_in[9];
    const float* lin_b = (const float*)d_in[10];
    float* out = (float*)d_out;
    (void)Wq_b;  // enters only via row-constant terms that cancel in softmax

    __half *key, *val, *qry, *G2, *P2, *KG, *VP, *VPT, *dist, *w, *wT;
    float *G2f, *P2f, *vv, *qq, *bb;
    cudaGetSymbolAddress((void**)&key, h_key);
    cudaGetSymbolAddress((void**)&val, h_val);
    cudaGetSymbolAddress((void**)&qry, h_qry);
    cudaGetSymbolAddress((void**)&G2f, g_G2f);
    cudaGetSymbolAddress((void**)&P2f, g_P2f);
    cudaGetSymbolAddress((void**)&G2, h_G2);
    cudaGetSymbolAddress((void**)&P2, h_P2);
    cudaGetSymbolAddress((void**)&vv, g_v);
    cudaGetSymbolAddress((void**)&qq, g_q);
    cudaGetSymbolAddress((void**)&bb, g_b);
    cudaGetSymbolAddress((void**)&KG, h_KG);
    cudaGetSymbolAddress((void**)&VP, h_VP);
    cudaGetSymbolAddress((void**)&VPT, h_VPT);
    cudaGetSymbolAddress((void**)&dist, h_dist);
    cudaGetSymbolAddress((void**)&w, h_w);
    cudaGetSymbolAddress((void**)&wT, h_wT);

    (void)cudaFuncSetAttribute(gemm_h<0>, cudaFuncAttributeMaxDynamicSharedMemorySize, SMEM_REQ);
    (void)cudaFuncSetAttribute(gemm_h<1>, cudaFuncAttributeMaxDynamicSharedMemorySize, SMEM_REQ);
    (void)cudaFuncSetAttribute(gemm_h<2>, cudaFuncAttributeMaxDynamicSharedMemorySize, SMEM_REQ);
    (void)cudaFuncSetAttribute(gemm_h<3>, cudaFuncAttributeMaxDynamicSharedMemorySize, SMEM_REQ);

    // fp16 copies of the big inputs
    cvt_h<<<(Bb*NK*D/8 + 255)/256, 256>>>(KEY,   key, Bb*NK*D/8);
    cvt_h<<<(Bb*NK*D/8 + 255)/256, 256>>>(VALUE, val, Bb*NK*D/8);
    cvt_h<<<(Bb*NQ*D/8 + 255)/256, 256>>>(QUERY, qry, Bb*NQ*D/8);

    // Folded weight products via split-K (fills the chip; was the 188us hotspot)
    cudaMemsetAsync(G2f, 0, 256 * 256 * sizeof(float), 0);
    cudaMemsetAsync(P2f, 0, 256 * 256 * sizeof(float), 0);
    small_gemm_splitk<1><<<dim3(8,8,16), 256>>>(Wq_w, Wk_w, G2f);   // G2[e,d]
    small_gemm_splitk<0><<<dim3(8,8,16), 256>>>(lin_w, Wv_w, P2f);  // P2[o,d]
    cvt_h<<<(256*256/8 + 255)/256, 256>>>(G2f, G2, 256*256/8);
    cvt_h<<<(256*256/8 + 255)/256, 256>>>(P2f, P2, 256*256/8);

    vecmat_col<<<1, 256>>>(Wk_b, Wq_w, vv);              // v[e]
    vecmat_row<<<256, 32>>>(Wv_b, lin_w, qq);            // q[o]
    bvec<<<Bb*NQ/256, 256>>>(qry, vv, bb);               // b[k]

    dim3 thr(256);

    // KG = KEYh · G2^T  -> fp16 [B*NK, 256]
    gemm_h<3><<<dim3(2, 128, 1), thr, SMEM_REQ>>>(
        key, G2, KG, nullptr, Bb*NK, 256, 256, 1.f, 0, 0, 0, 0);

    // VP = VALUEh · P2^T + q -> fp16 [B*NK, 256]
    gemm_h<0><<<dim3(2, 128, 1), thr, SMEM_REQ>>>(
        val, P2, VP, qq, Bb*NK, 256, 256, 1.f, 0, 0, 0, 0);

    // dist[b,i,k] = scale*(KG·Q^T + b[k]) -> fp16, batched
    gemm_h<1><<<dim3(16, 16, Bb), thr, SMEM_REQ>>>(
        KG, qry, dist, bb, NK, NQ, 256, scale,
        (long long)NK*256, (long long)NQ*256, (long long)NK*NQ, NQ);

    // softmax over k -> fp16 w
    softmax_h<<<Bb*NK, 256>>>(dist, w);

    // w[i,k] -> wT[k,i]
    transpose_h<<<dim3(NQ/64, NK/64, Bb), 256>>>(w, wT, NK, NQ,
        (long long)NK*NQ, (long long)NK*NQ);

    // VP[i,o] -> VPT[o,i] per batch
    transpose_h<<<dim3(256/64, NK/64, Bb), 256>>>(VP, VPT, NK, 256,
        (long long)NK*256, (long long)NK*256);

    // res[b,k,o] = wT·VPT^T + lin_b -> fp32 out
    gemm_h<2><<<dim3(2, 16, Bb), thr, SMEM_REQ>>>(
        wT, VPT, out, lin_b, NQ, 256, NK, 1.f,
        (long long)NK*NQ, (long long)NK*256, (long long)NQ*256, 0);
}

// round 10
// speedup vs baseline: 14.9648x; 1.1667x over previous
#include <cuda_runtime.h>
#include <cuda_fp16.h>
#include <cstdint>

// B=8, NK=NQ=2048, D=256, H=1024
// Folded algebra:
//   dist = scale*(KEY·G·QUERY^T + b_k)   (row-constants drop in softmax)
//   res  = w^T·(VALUE·P + q) + lin_b     (TN GEMM via ldmatrix.trans, no transposes)
// GEMM core: fp16 ops (mma.m16n8k16), fp32 accum.

#define KC     64
#define NSTG   3
#define TILE_B 16384
#define STG_B  (2 * TILE_B)
#define SMEM_REQ (NSTG * STG_B)      // 98304 B

// ---------------- scratch ----------------------------------------------------
__device__ __half h_key [8u*2048u*256u];
__device__ __half h_val [8u*2048u*256u];
__device__ __half h_qry [8u*2048u*256u];
__device__ float  g_G2f [256u*256u];          // fp32 split-K accumulators
__device__ float  g_P2f [256u*256u];
__device__ __half h_G2  [256u*256u];          // G2[e,d] = sum_h Wq[h,e]·Wk[h,d]
__device__ __half h_P2  [256u*256u];          // P2[o,d] = sum_h Wv[h,d]·lin[o,h]
__device__ float  g_v   [256];                // v[e] = sum_h bk[h]·Wq[h,e]
__device__ float  g_q   [256];                // q[o] = sum_h bv[h]·lin[o,h]
__device__ float  g_b   [8u*2048u];           // b[k] = sum_e Q[k,e]·v[e]
__device__ __half h_KG  [8u*2048u*256u];      // KEY·G
__device__ __half h_VP  [8u*2048u*256u];      // VALUE·P + q
__device__ __half h_dist[(size_t)8*2048*2048];
__device__ __half h_w   [(size_t)8*2048*2048];

// ---------------- PTX helpers -----------------------------------------------
__device__ __forceinline__ uint32_t smem_u32(const void* p) {
    uint32_t a;
    asm("{ .reg .u64 t; cvta.to.shared.u64 t, %1; cvt.u32.u64 %0, t; }" : "=r"(a) : "l"(p));
    return a;
}
__device__ __forceinline__ void cp16s(uint32_t s, const void* g) {
    asm volatile("cp.async.cg.shared.global [%0], [%1], 16;" :: "r"(s), "l"(g));
}
#define CP_COMMIT() asm volatile("cp.async.commit_group;")
#define CP_WAIT(n)  asm volatile("cp.async.wait_group %0;" :: "n"(n))

__device__ __forceinline__ void ldsm4(uint32_t& r0, uint32_t& r1, uint32_t& r2, uint32_t& r3,
                                      uint32_t addr) {
    asm volatile("ldmatrix.sync.aligned.m8n8.x4.shared.b16 {%0,%1,%2,%3}, [%4];"
                 : "=r"(r0), "=r"(r1), "=r"(r2), "=r"(r3) : "r"(addr));
}
__device__ __forceinline__ void ldsm4t(uint32_t& r0, uint32_t& r1, uint32_t& r2, uint32_t& r3,
                                       uint32_t addr) {
    asm volatile("ldmatrix.sync.aligned.m8n8.x4.trans.shared.b16 {%0,%1,%2,%3}, [%4];"
                 : "=r"(r0), "=r"(r1), "=r"(r2), "=r"(r3) : "r"(addr));
}
#define MMA_F16(c, a, b)                                                       \
    asm volatile(                                                              \
        "mma.sync.aligned.m16n8k16.row.col.f32.f16.f16.f32 "                   \
        "{%0,%1,%2,%3},{%4,%5,%6,%7},{%8,%9},{%0,%1,%2,%3};"                   \
        : "+f"(c[0]), "+f"(c[1]), "+f"(c[2]), "+f"(c[3])                       \
        : "r"(a[0]), "r"(a[1]), "r"(a[2]), "r"(a[3]), "r"(b[0]), "r"(b[1]))

// ---------------------------------------------------------------------------
// fp16 NT GEMM: tile 128x128, BK=64, 3-stage cp.async, 8 warps @ 64x32.
// EPI: 0 = +bias[n] -> half          (VP with q)
//      1 = (x+bias[n])*scale -> half (dist with b_k)
//      3 = plain -> half             (KG)
// ---------------------------------------------------------------------------
template <int EPI>
__global__ __launch_bounds__(256, 2) void gemm_h(
    const __half* __restrict__ Ag, const __half* __restrict__ Bg,
    void* __restrict__ Cg, const float* __restrict__ biasg,
    int M, int N, int K, float scale,
    long long sA, long long sB, long long sC, long long sBias)
{
    extern __shared__ char smem_raw[];
    const uint32_t sb = smem_u32(smem_raw);

    const int tid = threadIdx.x, lane = tid & 31, w = tid >> 5;
    const int wm = (w & 1) * 64;
    const int wn = (w >> 1) * 32;
    const __half* A  = Ag + (long long)blockIdx.z * sA;
    const __half* Bm = Bg + (long long)blockIdx.z * sB;
    const float* bias = biasg + (biasg ? (long long)blockIdx.z * sBias : 0);
    const long long cb = (long long)blockIdx.z * sC;
    const int m0 = blockIdx.y * 128, n0 = blockIdx.x * 128;

    float acc[4][4][4];
#pragma unroll
    for (int mt = 0; mt < 4; mt++)
#pragma unroll
        for (int nt = 0; nt < 4; nt++)
#pragma unroll
            for (int r = 0; r < 4; r++) acc[mt][nt][r] = 0.f;

    const int laneRowA = lane & 15;
    const int granA    = lane >> 4;
    const int swA      = laneRowA & 7;
    const int laneRowB = ((lane >> 4) << 3) + (lane & 7);
    const int granB    = (lane >> 3) & 1;
    const int swB      = lane & 7;

    auto load_chunk = [&](int c) {
        const int st = c % NSTG;
        const uint32_t sa  = sb + st * STG_B;
        const uint32_t sbu = sa + TILE_B;
        const char* ap = (const char*)A  + ((long long)m0 * K + (long long)c * KC) * 2;
        const char* bp = (const char*)Bm + ((long long)n0 * K + (long long)c * KC) * 2;
#pragma unroll
        for (int j = 0; j < 4; j++) {
            int gi = tid + 256 * j;
            int r = gi >> 3, g = gi & 7;
            uint32_t sw = (uint32_t)((g ^ (r & 7)) << 4) + (uint32_t)(r << 7);
            cp16s(sa  + sw, ap + (long long)r * K * 2 + g * 16);
            cp16s(sbu + sw, bp + (long long)r * K * 2 + g * 16);
        }
        CP_COMMIT();
    };

    const int C = K / KC;
    load_chunk(0); load_chunk(1);

    for (int c = 0; c < C; c++) {
        if (c + 2 < C) load_chunk(c + 2);

        if (c + 2 < C)      { CP_WAIT(2); }
        else if (c + 1 < C) { CP_WAIT(1); }
        else                { CP_WAIT(0); }
        __syncthreads();

        const uint32_t sa  = sb + (c % NSTG) * STG_B;
        const uint32_t sbu = sa + TILE_B;

#pragma unroll
        for (int ks = 0; ks < 4; ks++) {
            uint32_t bf[4][2];
#pragma unroll
            for (int np = 0; np < 2; np++) {
                int rB = wn + np * 16 + laneRowB;
                uint32_t addr = sbu + (uint32_t)(rB << 7)
                              + (uint32_t)((((ks << 1) + granB) ^ swB) << 4);
                ldsm4(bf[2 * np][0], bf[2 * np][1], bf[2 * np + 1][0], bf[2 * np + 1][1], addr);
            }
#pragma unroll
            for (int mt = 0; mt < 4; mt++) {
                int rA = wm + mt * 16 + laneRowA;
                uint32_t addr = sa + (uint32_t)(rA << 7)
                              + (uint32_t)((((ks << 1) + granA) ^ swA) << 4);
                uint32_t af[4];
                ldsm4(af[0], af[1], af[2], af[3], addr);
#pragma unroll
                for (int nt = 0; nt < 4; nt++)
                    MMA_F16(acc[mt][nt], af, bf[nt]);
            }
        }
        __syncthreads();
    }

    const int gr = lane >> 2, t4 = lane & 3;
#pragma unroll
    for (int mt = 0; mt < 4; mt++) {
        int r = m0 + wm + mt * 16 + gr;
#pragma unroll
        for (int nt = 0; nt < 4; nt++) {
            int cidx = n0 + wn + nt * 8 + 2 * t4;
            float x0 = acc[mt][nt][0], x1 = acc[mt][nt][1];
            float x2 = acc[mt][nt][2], x3 = acc[mt][nt][3];
            if (EPI == 0 || EPI == 1) {
                float b0 = bias[cidx], b1 = bias[cidx + 1];
                x0 += b0; x1 += b1; x2 += b0; x3 += b1;
            }
            if (EPI == 1) { x0 *= scale; x1 *= scale; x2 *= scale; x3 *= scale; }
            __half* Co = (__half*)Cg + cb;
            *(__half2*)(Co + (long long)r * N + cidx) = __floats2half2_rn(x0, x1);
            *(__half2*)(Co + (long long)(r + 8) * N + cidx) = __floats2half2_rn(x2, x3);
        }
    }
}

// ---------------------------------------------------------------------------
// TN res GEMM via ldmatrix.trans: out[k,o] = sum_i w[i,k]·VP[i,o] + lin_b[o].
// Tiles stored i-major in smem: 64(i) x 128 cols, 256B rows, granule-XOR swizzle.
// grid (N/128, M/128, batch), 8 warps @ 64(m) x 32(n), fp32 out.
// ---------------------------------------------------------------------------
__global__ __launch_bounds__(256, 2) void gemm_tn_res(
    const __half* __restrict__ wg, const __half* __restrict__ vpg,
    float* __restrict__ outg, const float* __restrict__ bias,
    int M, int N, int K,
    long long sW, long long sV, long long sO)
{
    extern __shared__ char smem_raw[];
    const uint32_t sb = smem_u32(smem_raw);

    const int tid = threadIdx.x, lane = tid & 31, w = tid >> 5;
    const int wm = (w & 1) * 64;
    const int wn = (w >> 1) * 32;
    const __half* W  = wg  + (long long)blockIdx.z * sW;   // [i, k] row-major (k stride M)
    const __half* V  = vpg + (long long)blockIdx.z * sV;   // [i, o] row-major (o stride N)
    float* Out       = outg + (long long)blockIdx.z * sO;
    const int m0 = blockIdx.y * 128, n0 = blockIdx.x * 128;

    float acc[4][4][4];
#pragma unroll
    for (int mt = 0; mt < 4; mt++)
#pragma unroll
        for (int nt = 0; nt < 4; nt++)
#pragma unroll
            for (int r = 0; r < 4; r++) acc[mt][nt][r] = 0.f;

    // trans-ldmatrix per-lane invariants
    const int iA = ((lane >> 4) << 3) + (lane & 7);   // i offset within 16-slice (A)
    const int mA = (lane >> 3) & 1;                   // m granule half (A)
    const int iB = (((lane >> 3) & 1) << 3) + (lane & 7);  // i offset (B)
    const int oB = lane >> 4;                         // o granule half (B)

    auto load_chunk = [&](int c) {
        const int st = c % NSTG;
        const uint32_t sa  = sb + st * STG_B;          // A tile: w[i0+r][m0..m0+127]
        const uint32_t sbu = sa + TILE_B;              // B tile: VP[i0+r][n0..n0+127]
        const int i0 = c * KC;
        const char* ap = (const char*)W + ((long long)i0 * M + m0) * 2;
        const char* bp = (const char*)V + ((long long)i0 * N + n0) * 2;
#pragma unroll
        for (int j = 0; j < 4; j++) {
            int gi = tid + 256 * j;                    // 0..1023
            int r = gi >> 4, g = gi & 15;              // 64 rows x 16 granules
            uint32_t sw = (uint32_t)(r << 8) + (uint32_t)((g ^ (r & 7)) << 4);
            cp16s(sa  + sw, ap + (long long)r * M * 2 + g * 16);
            cp16s(sbu + sw, bp + (long long)r * N * 2 + g * 16);
        }
        CP_COMMIT();
    };

    const int C = K / KC;
    load_chunk(0); load_chunk(1);

    for (int c = 0; c < C; c++) {
        if (c + 2 < C) load_chunk(c + 2);

        if (c + 2 < C)      { CP_WAIT(2); }
        else if (c + 1 < C) { CP_WAIT(1); }
        else                { CP_WAIT(0); }
        __syncthreads();

        const uint32_t sa  = sb + (c % NSTG) * STG_B;
        const uint32_t sbu = sa + TILE_B;

#pragma unroll
        for (int ks = 0; ks < 4; ks++) {
            // B frags (trans): source rows i, cols o
            uint32_t bf[4][2];
#pragma unroll
            for (int np = 0; np < 2; np++) {
                int il = ks * 16 + iB;
                int oc = wn + np * 16 + oB * 8;
                uint32_t addr = sbu + (uint32_t)(il << 8)
                              + (uint32_t)(((oc >> 3) ^ (il & 7)) << 4);
                ldsm4t(bf[2 * np][0], bf[2 * np][1], bf[2 * np + 1][0], bf[2 * np + 1][1], addr);
            }
            // A frags (trans): source rows i, cols m
#pragma unroll
            for (int mt = 0; mt < 4; mt++) {
                int il = ks * 16 + iA;
                int mc = wm + mt * 16 + mA * 8;
                uint32_t addr = sa + (uint32_t)(il << 8)
                              + (uint32_t)(((mc >> 3) ^ (il & 7)) << 4);
                uint32_t af[4];
                ldsm4t(af[0], af[1], af[2], af[3], addr);
#pragma unroll
                for (int nt = 0; nt < 4; nt++)
                    MMA_F16(acc[mt][nt], af, bf[nt]);
            }
        }
        __syncthreads();
    }

    const int gr = lane >> 2, t4 = lane & 3;
#pragma unroll
    for (int mt = 0; mt < 4; mt++) {
        int r = m0 + wm + mt * 16 + gr;
#pragma unroll
        for (int nt = 0; nt < 4; nt++) {
            int cidx = n0 + wn + nt * 8 + 2 * t4;
            float b0 = bias[cidx], b1 = bias[cidx + 1];
            float x0 = acc[mt][nt][0] + b0, x1 = acc[mt][nt][1] + b1;
            float x2 = acc[mt][nt][2] + b0, x3 = acc[mt][nt][3] + b1;
            *(float2*)(Out + (long long)r * N + cidx) = make_float2(x0, x1);
            *(float2*)(Out + (long long)(r + 8) * N + cidx) = make_float2(x2, x3);
        }
    }
}

// ---------------------------------------------------------------------------
// Split-K small GEMM (256x256 out, K=1024), fp32, atomicAdd partials.
// ---------------------------------------------------------------------------
template <int TRANSA>
__global__ __launch_bounds__(256) void small_gemm_splitk(
    const float* __restrict__ A, const float* __restrict__ B, float* __restrict__ Cf)
{
    __shared__ float sA[64][33], sB[64][33];
    const int e0 = blockIdx.x * 32, d0 = blockIdx.y * 32, h0 = blockIdx.z * 64;
    const int tid = threadIdx.x;

#pragma unroll
    for (int j = 0; j < 8; j++) {
        int li = tid + 256 * j;
        if (TRANSA) {
            int r = li >> 5, cl = li & 31;
            sA[r][cl] = A[(h0 + r) * 256 + e0 + cl];
        } else {
            int cl = li >> 6, r = li & 63;
            sA[r][cl] = A[(e0 + cl) * 1024 + h0 + r];
        }
        int r = li >> 5, cl = li & 31;
        sB[r][cl] = B[(h0 + r) * 256 + d0 + cl];
    }
    __syncthreads();

    const int tx = tid & 15, ty = tid >> 4;
    float acc[2][2] = {{0.f, 0.f}, {0.f, 0.f}};
#pragma unroll
    for (int h = 0; h < 64; h++) {
        float a0 = sA[h][ty * 2], a1 = sA[h][ty * 2 + 1];
        float b0 = sB[h][tx * 2], b1 = sB[h][tx * 2 + 1];
        acc[0][0] += a0 * b0; acc[0][1] += a0 * b1;
        acc[1][0] += a1 * b0; acc[1][1] += a1 * b1;
    }
#pragma unroll
    for (int i = 0; i < 2; i++)
#pragma unroll
        for (int j = 0; j < 2; j++)
            atomicAdd(&Cf[(e0 + ty * 2 + i) * 256 + d0 + tx * 2 + j], acc[i][j]);
}

// fp32 -> fp16 elementwise (8 per thread)
__global__ void cvt_h(const float* __restrict__ in, __half* __restrict__ out, int n8)
{
    int i = blockIdx.x * blockDim.x + threadIdx.x;
    if (i < n8) {
        float4 a = ((const float4*)in)[2 * i];
        float4 b = ((const float4*)in)[2 * i + 1];
        __half2 h[4] = { __floats2half2_rn(a.x, a.y), __floats2half2_rn(a.z, a.w),
                         __floats2half2_rn(b.x, b.y), __floats2half2_rn(b.z, b.w) };
        ((uint4*)out)[i] = *(uint4*)h;
    }
}

// v[e] = sum_h vec[h]·W[h*256+e]
__global__ void vecmat_col(const float* __restrict__ vec, const float* __restrict__ W,
                           float* __restrict__ o)
{
    int e = threadIdx.x;
    float acc = 0.f;
#pragma unroll 8
    for (int h = 0; h < 1024; h++) acc += vec[h] * W[h * 256 + e];
    o[e] = acc;
}

// q[o] = sum_h vec[h]·W[o*1024+h]
__global__ void vecmat_row(const float* __restrict__ vec, const float* __restrict__ W,
                           float* __restrict__ o)
{
    int ob = blockIdx.x, lane = threadIdx.x;
    float acc = 0.f;
    for (int h = lane; h < 1024; h += 32) acc += vec[h] * W[ob * 1024 + h];
#pragma unroll
    for (int of = 16; of > 0; of >>= 1) acc += __shfl_xor_sync(0xffffffffu, acc, of);
    if (lane == 0) o[ob] = acc;
}

// b[k] = sum_e Q[k*256+e]·v[e]
__global__ __launch_bounds__(256) void bvec(const __half* __restrict__ Q,
                                            const float* __restrict__ v,
                                            float* __restrict__ ob)
{
    __shared__ float sv[256];
    sv[threadIdx.x] = v[threadIdx.x];
    __syncthreads();
    int k = blockIdx.x * 256 + threadIdx.x;
    const __half* row = Q + (long long)k * 256;
    float acc = 0.f;
#pragma unroll 16
    for (int e = 0; e < 256; e += 2) {
        __half2 h2 = *(const __half2*)(row + e);
        acc += __low2float(h2) * sv[e] + __high2float(h2) * sv[e + 1];
    }
    ob[k] = acc;
}

// ---------------------------------------------------------------------------
// Row softmax over 2048 fp16 logits -> fp16 weights
// ---------------------------------------------------------------------------
__global__ __launch_bounds__(256) void softmax_h(const __half* __restrict__ d,
                                                 __half* __restrict__ o)
{
    long long row = blockIdx.x;
    const __half* p = d + row * 2048ll;
    __half* q = o + row * 2048ll;
    int t = threadIdx.x;

    float v[8];
    float m = -1e30f;
#pragma unroll
    for (int j = 0; j < 8; j++) { v[j] = __half2float(p[t + (j << 8)]); m = fmaxf(m, v[j]); }
#pragma unroll
    for (int of = 16; of > 0; of >>= 1) m = fmaxf(m, __shfl_xor_sync(0xffffffffu, m, of));
    __shared__ float redm[8];
    if ((t & 31) == 0) redm[t >> 5] = m;
    __syncthreads();
#pragma unroll
    for (int w2 = 0; w2 < 8; w2++) m = fmaxf(m, redm[w2]);

    float s = 0.f;
#pragma unroll
    for (int j = 0; j < 8; j++) { v[j] = __expf(v[j] - m); s += v[j]; }
#pragma unroll
    for (int of = 16; of > 0; of >>= 1) s += __shfl_xor_sync(0xffffffffu, s, of);
    __shared__ float reds[8];
    if ((t & 31) == 0) reds[t >> 5] = s;
    __syncthreads();
    s = 0.f;
#pragma unroll
    for (int w2 = 0; w2 < 8; w2++) s += reds[w2];
    float inv = 1.f / s;
#pragma unroll
    for (int j = 0; j < 8; j++) q[t + (j << 8)] = __float2half_rn(v[j] * inv);
}

// ---------------------------------------------------------------------------
extern "C" void kernel_launch(void* const* d_in, const int* in_sizes, int n_in,
                              void* d_out, int out_size)
{
    const int Bb = 8, NK = 2048, NQ = 2048, D = 256, H = 1024;
    const float scale = 1.0f / 32.0f;

    const float* KEY   = (const float*)d_in[0];
    const float* VALUE = (const float*)d_in[1];
    const float* QUERY = (const float*)d_in[2];
    const float* Wk_w  = (const float*)d_in[3];
    const float* Wk_b  = (const float*)d_in[4];
    const float* Wq_w  = (const float*)d_in[5];
    const float* Wq_b  = (const float*)d_in[6];
    const float* Wv_w  = (const float*)d_in[7];
    const float* Wv_b  = (const float*)d_in[8];
    const float* lin_w = (const float*)d_in[9];
    const float* lin_b = (const float*)d_in[10];
    float* out = (float*)d_out;
    (void)Wq_b;  // enters only via row-constant terms that cancel in softmax

    __half *key, *val, *qry, *G2, *P2, *KG, *VP, *dist, *w;
    float *G2f, *P2f, *vv, *qq, *bb;
    cudaGetSymbolAddress((void**)&key, h_key);
    cudaGetSymbolAddress((void**)&val, h_val);
    cudaGetSymbolAddress((void**)&qry, h_qry);
    cudaGetSymbolAddress((void**)&G2f, g_G2f);
    cudaGetSymbolAddress((void**)&P2f, g_P2f);
    cudaGetSymbolAddress((void**)&G2, h_G2);
    cudaGetSymbolAddress((void**)&P2, h_P2);
    cudaGetSymbolAddress((void**)&vv, g_v);
    cudaGetSymbolAddress((void**)&qq, g_q);
    cudaGetSymbolAddress((void**)&bb, g_b);
    cudaGetSymbolAddress((void**)&KG, h_KG);
    cudaGetSymbolAddress((void**)&VP, h_VP);
    cudaGetSymbolAddress((void**)&dist, h_dist);
    cudaGetSymbolAddress((void**)&w, h_w);

    (void)cudaFuncSetAttribute(gemm_h<0>, cudaFuncAttributeMaxDynamicSharedMemorySize, SMEM_REQ);
    (void)cudaFuncSetAttribute(gemm_h<1>, cudaFuncAttributeMaxDynamicSharedMemorySize, SMEM_REQ);
    (void)cudaFuncSetAttribute(gemm_h<3>, cudaFuncAttributeMaxDynamicSharedMemorySize, SMEM_REQ);
    (void)cudaFuncSetAttribute(gemm_tn_res, cudaFuncAttributeMaxDynamicSharedMemorySize, SMEM_REQ);

    // fp16 copies of the big inputs
    cvt_h<<<(Bb*NK*D/8 + 255)/256, 256>>>(KEY,   key, Bb*NK*D/8);
    cvt_h<<<(Bb*NK*D/8 + 255)/256, 256>>>(VALUE, val, Bb*NK*D/8);
    cvt_h<<<(Bb*NQ*D/8 + 255)/256, 256>>>(QUERY, qry, Bb*NQ*D/8);

    // Folded weight products via split-K
    cudaMemsetAsync(G2f, 0, 256 * 256 * sizeof(float), 0);
    cudaMemsetAsync(P2f, 0, 256 * 256 * sizeof(float), 0);
    small_gemm_splitk<1><<<dim3(8,8,16), 256>>>(Wq_w, Wk_w, G2f);   // G2[e,d]
    small_gemm_splitk<0><<<dim3(8,8,16), 256>>>(lin_w, Wv_w, P2f);  // P2[o,d]
    cvt_h<<<(256*256/8 + 255)/256, 256>>>(G2f, G2, 256*256/8);
    cvt_h<<<(256*256/8 + 255)/256, 256>>>(P2f, P2, 256*256/8);

    vecmat_col<<<1, 256>>>(Wk_b, Wq_w, vv);              // v[e]
    vecmat_row<<<256, 32>>>(Wv_b, lin_w, qq);            // q[o]
    bvec<<<Bb*NQ/256, 256>>>(qry, vv, bb);               // b[k]

    dim3 thr(256);

    // KG = KEYh · G2^T  -> fp16 [B*NK, 256]
    gemm_h<3><<<dim3(2, 128, 1), thr, SMEM_REQ>>>(
        key, G2, KG, nullptr, Bb*NK, 256, 256, 1.f, 0, 0, 0, 0);

    // VP = VALUEh · P2^T + q -> fp16 [B*NK, 256]
    gemm_h<0><<<dim3(2, 128, 1), thr, SMEM_REQ>>>(
        val, P2, VP, qq, Bb*NK, 256, 256, 1.f, 0, 0, 0, 0);

    // dist[b,i,k] = scale*(KG·Q^T + b[k]) -> fp16, batched
    gemm_h<1><<<dim3(16, 16, Bb), thr, SMEM_REQ>>>(
        KG, qry, dist, bb, NK, NQ, 256, scale,
        (long long)NK*256, (long long)NQ*256, (long long)NK*NQ, NQ);

    // softmax over k -> fp16 w[i,k]
    softmax_h<<<Bb*NK, 256>>>(dist, w);

    // res[b,k,o] = sum_i w[i,k]·VP[i,o] + lin_b  (TN, no transposes) -> fp32 out
    gemm_tn_res<<<dim3(2, 16, Bb), thr, SMEM_REQ>>>(
        w, VP, out, lin_b, NQ, 256, NK,
        (long long)NK*NQ, (long long)NK*256, (long long)NQ*256);
}

// round 16
// speedup vs baseline: 17.2184x; 1.1506x over previous
#include <cuda_runtime.h>
#include <cuda_fp16.h>
#include <cstdint>

// B=8, NK=NQ=2048, D=256, H=1024
// Folded algebra:
//   dist = scale*(KEY·G·QUERY^T + b_k)   (row-constants drop in softmax)
//   res  = w^T·(VALUE·P + q) + lin_b     (TN GEMM via ldmatrix.trans)
// GEMM core: fp16 ops (mma.m16n8k16), fp32 accum.

#define KC     64
#define NSTG   3
#define TILE_B 16384
#define STG_B  (2 * TILE_B)
#define SMEM_REQ (NSTG * STG_B)      // 98304 B

// ---------------- scratch ----------------------------------------------------
__device__ __half h_key [8u*2048u*256u];
__device__ __half h_val [8u*2048u*256u];
__device__ __half h_qry [8u*2048u*256u];
__device__ float  g_G2f [256u*256u];
__device__ float  g_P2f [256u*256u];
__device__ __half h_G2  [256u*256u];          // G2[e,d] = sum_h Wq[h,e]·Wk[h,d]
__device__ __half h_P2  [256u*256u];          // P2[o,d] = sum_h Wv[h,d]·lin[o,h]
__device__ float  g_v   [256];                // v[e] = sum_h bk[h]·Wq[h,e]
__device__ float  g_q   [256];                // q[o] = sum_h bv[h]·lin[o,h]
__device__ float  g_b   [8u*2048u];           // b[k] = sum_e Q[k,e]·v[e]
__device__ __half h_KG  [8u*2048u*256u];      // KEY·G
__device__ __half h_VP  [8u*2048u*256u];      // VALUE·P + q
__device__ __half h_dist[(size_t)8*2048*2048];
__device__ __half h_w   [(size_t)8*2048*2048];

// ---------------- PTX helpers -----------------------------------------------
__device__ __forceinline__ uint32_t smem_u32(const void* p) {
    uint32_t a;
    asm("{ .reg .u64 t; cvta.to.shared.u64 t, %1; cvt.u32.u64 %0, t; }" : "=r"(a) : "l"(p));
    return a;
}
__device__ __forceinline__ void cp16s(uint32_t s, const void* g) {
    asm volatile("cp.async.cg.shared.global [%0], [%1], 16;" :: "r"(s), "l"(g));
}
#define CP_COMMIT() asm volatile("cp.async.commit_group;")
#define CP_WAIT(n)  asm volatile("cp.async.wait_group %0;" :: "n"(n))

__device__ __forceinline__ void ldsm4(uint32_t& r0, uint32_t& r1, uint32_t& r2, uint32_t& r3,
                                      uint32_t addr) {
    asm volatile("ldmatrix.sync.aligned.m8n8.x4.shared.b16 {%0,%1,%2,%3}, [%4];"
                 : "=r"(r0), "=r"(r1), "=r"(r2), "=r"(r3) : "r"(addr));
}
__device__ __forceinline__ void ldsm4t(uint32_t& r0, uint32_t& r1, uint32_t& r2, uint32_t& r3,
                                       uint32_t addr) {
    asm volatile("ldmatrix.sync.aligned.m8n8.x4.trans.shared.b16 {%0,%1,%2,%3}, [%4];"
                 : "=r"(r0), "=r"(r1), "=r"(r2), "=r"(r3) : "r"(addr));
}
#define MMA_F16(c, a, b)                                                       \
    asm volatile(                                                              \
        "mma.sync.aligned.m16n8k16.row.col.f32.f16.f16.f32 "                   \
        "{%0,%1,%2,%3},{%4,%5,%6,%7},{%8,%9},{%0,%1,%2,%3};"                   \
        : "+f"(c[0]), "+f"(c[1]), "+f"(c[2]), "+f"(c[3])                       \
        : "r"(a[0]), "r"(a[1]), "r"(a[2]), "r"(a[3]), "r"(b[0]), "r"(b[1]))

// ---------------------------------------------------------------------------
// fp16 NT GEMM: tile 128x128, BK=64, 3-stage cp.async, 8 warps @ 64x32.
// EPI: 0 = +bias[n] -> half          (VP with q)
//      1 = (x+bias[n])*scale -> half (dist with b_k)
//      3 = plain -> half             (KG)
// (verbatim from the 261.6us R10 kernel)
// ---------------------------------------------------------------------------
template <int EPI>
__global__ __launch_bounds__(256, 2) void gemm_h(
    const __half* __restrict__ Ag, const __half* __restrict__ Bg,
    void* __restrict__ Cg, const float* __restrict__ biasg,
    int M, int N, int K, float scale,
    long long sA, long long sB, long long sC, long long sBias)
{
    extern __shared__ char smem_raw[];
    const uint32_t sb = smem_u32(smem_raw);

    const int tid = threadIdx.x, lane = tid & 31, w = tid >> 5;
    const int wm = (w & 1) * 64;
    const int wn = (w >> 1) * 32;
    const __half* A  = Ag + (long long)blockIdx.z * sA;
    const __half* Bm = Bg + (long long)blockIdx.z * sB;
    const float* bias = biasg + (biasg ? (long long)blockIdx.z * sBias : 0);
    const long long cb = (long long)blockIdx.z * sC;
    const int m0 = blockIdx.y * 128, n0 = blockIdx.x * 128;

    float acc[4][4][4];
#pragma unroll
    for (int mt = 0; mt < 4; mt++)
#pragma unroll
        for (int nt = 0; nt < 4; nt++)
#pragma unroll
            for (int r = 0; r < 4; r++) acc[mt][nt][r] = 0.f;

    const int laneRowA = lane & 15;
    const int granA    = lane >> 4;
    const int swA      = laneRowA & 7;
    const int laneRowB = ((lane >> 4) << 3) + (lane & 7);
    const int granB    = (lane >> 3) & 1;
    const int swB      = lane & 7;

    auto load_chunk = [&](int c) {
        const int st = c % NSTG;
        const uint32_t sa  = sb + st * STG_B;
        const uint32_t sbu = sa + TILE_B;
        const char* ap = (const char*)A  + ((long long)m0 * K + (long long)c * KC) * 2;
        const char* bp = (const char*)Bm + ((long long)n0 * K + (long long)c * KC) * 2;
#pragma unroll
        for (int j = 0; j < 4; j++) {
            int gi = tid + 256 * j;
            int r = gi >> 3, g = gi & 7;
            uint32_t sw = (uint32_t)((g ^ (r & 7)) << 4) + (uint32_t)(r << 7);
            cp16s(sa  + sw, ap + (long long)r * K * 2 + g * 16);
            cp16s(sbu + sw, bp + (long long)r * K * 2 + g * 16);
        }
        CP_COMMIT();
    };

    const int C = K / KC;
    load_chunk(0); load_chunk(1);

    for (int c = 0; c < C; c++) {
        if (c + 2 < C) load_chunk(c + 2);

        if (c + 2 < C)      { CP_WAIT(2); }
        else if (c + 1 < C) { CP_WAIT(1); }
        else                { CP_WAIT(0); }
        __syncthreads();

        const uint32_t sa  = sb + (c % NSTG) * STG_B;
        const uint32_t sbu = sa + TILE_B;

#pragma unroll
        for (int ks = 0; ks < 4; ks++) {
            uint32_t bf[4][2];
#pragma unroll
            for (int np = 0; np < 2; np++) {
                int rB = wn + np * 16 + laneRowB;
                uint32_t addr = sbu + (uint32_t)(rB << 7)
                              + (uint32_t)((((ks << 1) + granB) ^ swB) << 4);
                ldsm4(bf[2 * np][0], bf[2 * np][1], bf[2 * np + 1][0], bf[2 * np + 1][1], addr);
            }
#pragma unroll
            for (int mt = 0; mt < 4; mt++) {
                int rA = wm + mt * 16 + laneRowA;
                uint32_t addr = sa + (uint32_t)(rA << 7)
                              + (uint32_t)((((ks << 1) + granA) ^ swA) << 4);
                uint32_t af[4];
                ldsm4(af[0], af[1], af[2], af[3], addr);
#pragma unroll
                for (int nt = 0; nt < 4; nt++)
                    MMA_F16(acc[mt][nt], af, bf[nt]);
            }
        }
        __syncthreads();
    }

    const int gr = lane >> 2, t4 = lane & 3;
#pragma unroll
    for (int mt = 0; mt < 4; mt++) {
        int r = m0 + wm + mt * 16 + gr;
#pragma unroll
        for (int nt = 0; nt < 4; nt++) {
            int cidx = n0 + wn + nt * 8 + 2 * t4;
            float x0 = acc[mt][nt][0], x1 = acc[mt][nt][1];
            float x2 = acc[mt][nt][2], x3 = acc[mt][nt][3];
            if (EPI == 0 || EPI == 1) {
                float b0 = bias[cidx], b1 = bias[cidx + 1];
                x0 += b0; x1 += b1; x2 += b0; x3 += b1;
            }
            if (EPI == 1) { x0 *= scale; x1 *= scale; x2 *= scale; x3 *= scale; }
            __half* Co = (__half*)Cg + cb;
            *(__half2*)(Co + (long long)r * N + cidx) = __floats2half2_rn(x0, x1);
            *(__half2*)(Co + (long long)(r + 8) * N + cidx) = __floats2half2_rn(x2, x3);
        }
    }
}

// ---------------------------------------------------------------------------
// TN res GEMM via ldmatrix.trans: out[k,o] = sum_i w[i,k]·VP[i,o] + lin_b[o].
// (verbatim from the 261.6us R10 kernel)
// ---------------------------------------------------------------------------
__global__ __launch_bounds__(256, 2) void gemm_tn_res(
    const __half* __restrict__ wg, const __half* __restrict__ vpg,
    float* __restrict__ outg, const float* __restrict__ bias,
    int M, int N, int K,
    long long sW, long long sV, long long sO)
{
    extern __shared__ char smem_raw[];
    const uint32_t sb = smem_u32(smem_raw);

    const int tid = threadIdx.x, lane = tid & 31, w = tid >> 5;
    const int wm = (w & 1) * 64;
    const int wn = (w >> 1) * 32;
    const __half* W  = wg  + (long long)blockIdx.z * sW;
    const __half* V  = vpg + (long long)blockIdx.z * sV;
    float* Out       = outg + (long long)blockIdx.z * sO;
    const int m0 = blockIdx.y * 128, n0 = blockIdx.x * 128;

    float acc[4][4][4];
#pragma unroll
    for (int mt = 0; mt < 4; mt++)
#pragma unroll
        for (int nt = 0; nt < 4; nt++)
#pragma unroll
            for (int r = 0; r < 4; r++) acc[mt][nt][r] = 0.f;

    const int iA = ((lane >> 4) << 3) + (lane & 7);
    const int mA = (lane >> 3) & 1;
    const int iB = (((lane >> 3) & 1) << 3) + (lane & 7);
    const int oB = lane >> 4;

    auto load_chunk = [&](int c) {
        const int st = c % NSTG;
        const uint32_t sa  = sb + st * STG_B;
        const uint32_t sbu = sa + TILE_B;
        const int i0 = c * KC;
        const char* ap = (const char*)W + ((long long)i0 * M + m0) * 2;
        const char* bp = (const char*)V + ((long long)i0 * N + n0) * 2;
#pragma unroll
        for (int j = 0; j < 4; j++) {
            int gi = tid + 256 * j;
            int r = gi >> 4, g = gi & 15;
            uint32_t sw = (uint32_t)(r << 8) + (uint32_t)((g ^ (r & 7)) << 4);
            cp16s(sa  + sw, ap + (long long)r * M * 2 + g * 16);
            cp16s(sbu + sw, bp + (long long)r * N * 2 + g * 16);
        }
        CP_COMMIT();
    };

    const int C = K / KC;
    load_chunk(0); load_chunk(1);

    for (int c = 0; c < C; c++) {
        if (c + 2 < C) load_chunk(c + 2);

        if (c + 2 < C)      { CP_WAIT(2); }
        else if (c + 1 < C) { CP_WAIT(1); }
        else                { CP_WAIT(0); }
        __syncthreads();

        const uint32_t sa  = sb + (c % NSTG) * STG_B;
        const uint32_t sbu = sa + TILE_B;

#pragma unroll
        for (int ks = 0; ks < 4; ks++) {
            uint32_t bf[4][2];
#pragma unroll
            for (int np = 0; np < 2; np++) {
                int il = ks * 16 + iB;
                int oc = wn + np * 16 + oB * 8;
                uint32_t addr = sbu + (uint32_t)(il << 8)
                              + (uint32_t)(((oc >> 3) ^ (il & 7)) << 4);
                ldsm4t(bf[2 * np][0], bf[2 * np][1], bf[2 * np + 1][0], bf[2 * np + 1][1], addr);
            }
#pragma unroll
            for (int mt = 0; mt < 4; mt++) {
                int il = ks * 16 + iA;
                int mc = wm + mt * 16 + mA * 8;
                uint32_t addr = sa + (uint32_t)(il << 8)
                              + (uint32_t)(((mc >> 3) ^ (il & 7)) << 4);
                uint32_t af[4];
                ldsm4t(af[0], af[1], af[2], af[3], addr);
#pragma unroll
                for (int nt = 0; nt < 4; nt++)
                    MMA_F16(acc[mt][nt], af, bf[nt]);
            }
        }
        __syncthreads();
    }

    const int gr = lane >> 2, t4 = lane & 3;
#pragma unroll
    for (int mt = 0; mt < 4; mt++) {
        int r = m0 + wm + mt * 16 + gr;
#pragma unroll
        for (int nt = 0; nt < 4; nt++) {
            int cidx = n0 + wn + nt * 8 + 2 * t4;
            float b0 = bias[cidx], b1 = bias[cidx + 1];
            float x0 = acc[mt][nt][0] + b0, x1 = acc[mt][nt][1] + b1;
            float x2 = acc[mt][nt][2] + b0, x3 = acc[mt][nt][3] + b1;
            *(float2*)(Out + (long long)r * N + cidx) = make_float2(x0, x1);
            *(float2*)(Out + (long long)(r + 8) * N + cidx) = make_float2(x2, x3);
        }
    }
}

// ---------------------------------------------------------------------------
// Merged split-K small GEMMs: z<16 -> G2f (A: [1024,256] used transposed),
// z>=16 -> P2f (A: [256,1024]). 32x32 tile, K-chunk 64, fp32 atomicAdd.
// ---------------------------------------------------------------------------
__global__ __launch_bounds__(256) void small_gemm_splitk2(
    const float* __restrict__ Wq, const float* __restrict__ Wk,
    const float* __restrict__ lin, const float* __restrict__ Wv,
    float* __restrict__ G2f, float* __restrict__ P2f)
{
    __shared__ float sA[64][33], sB[64][33];
    const int e0 = blockIdx.x * 32, d0 = blockIdx.y * 32;
    const int zz = blockIdx.z;
    const bool first = (zz < 16);
    const int h0 = (first ? zz : zz - 16) * 64;
    const float* A = first ? Wq : lin;
    const float* B = first ? Wk : Wv;
    float* Cf = first ? G2f : P2f;
    const int tid = threadIdx.x;

#pragma unroll
    for (int j = 0; j < 8; j++) {
        int li = tid + 256 * j;
        if (first) {                           // A: [1024,256], sA[h][e]
            int r = li >> 5, cl = li & 31;
            sA[r][cl] = A[(h0 + r) * 256 + e0 + cl];
        } else {                               // A: [256,1024], sA[h][o]
            int cl = li >> 6, r = li & 63;
            sA[r][cl] = A[(e0 + cl) * 1024 + h0 + r];
        }
        int r = li >> 5, cl = li & 31;
        sB[r][cl] = B[(h0 + r) * 256 + d0 + cl];
    }
    __syncthreads();

    const int tx = tid & 15, ty = tid >> 4;
    float acc[2][2] = {{0.f, 0.f}, {0.f, 0.f}};
#pragma unroll
    for (int h = 0; h < 64; h++) {
        float a0 = sA[h][ty * 2], a1 = sA[h][ty * 2 + 1];
        float b0 = sB[h][tx * 2], b1 = sB[h][tx * 2 + 1];
        acc[0][0] += a0 * b0; acc[0][1] += a0 * b1;
        acc[1][0] += a1 * b0; acc[1][1] += a1 * b1;
    }
#pragma unroll
    for (int i = 0; i < 2; i++)
#pragma unroll
        for (int j = 0; j < 2; j++)
            atomicAdd(&Cf[(e0 + ty * 2 + i) * 256 + d0 + tx * 2 + j], acc[i][j]);
}

// merged fp32->fp16 x3 (blockIdx.y selects tensor)
__global__ void cvt_h3(const float* __restrict__ a, __half* __restrict__ oa,
                       const float* __restrict__ b, __half* __restrict__ ob,
                       const float* __restrict__ c, __half* __restrict__ oc, int n8)
{
    int i = blockIdx.x * blockDim.x + threadIdx.x;
    if (i >= n8) return;
    const float* in = (blockIdx.y == 0) ? a : (blockIdx.y == 1) ? b : c;
    __half* out     = (blockIdx.y == 0) ? oa : (blockIdx.y == 1) ? ob : oc;
    float4 x = ((const float4*)in)[2 * i];
    float4 y = ((const float4*)in)[2 * i + 1];
    __half2 h[4] = { __floats2half2_rn(x.x, x.y), __floats2half2_rn(x.z, x.w),
                     __floats2half2_rn(y.x, y.y), __floats2half2_rn(y.z, y.w) };
    ((uint4*)out)[i] = *(uint4*)h;
}

// merged fp32->fp16 x2
__global__ void cvt_h2(const float* __restrict__ a, __half* __restrict__ oa,
                       const float* __restrict__ b, __half* __restrict__ ob, int n8)
{
    int i = blockIdx.x * blockDim.x + threadIdx.x;
    if (i >= n8) return;
    const float* in = blockIdx.y ? b : a;
    __half* out     = blockIdx.y ? ob : oa;
    float4 x = ((const float4*)in)[2 * i];
    float4 y = ((const float4*)in)[2 * i + 1];
    __half2 h[4] = { __floats2half2_rn(x.x, x.y), __floats2half2_rn(x.z, x.w),
                     __floats2half2_rn(y.x, y.y), __floats2half2_rn(y.z, y.w) };
    ((uint4*)out)[i] = *(uint4*)h;
}

// v[e] += sum_{h in block} vec[h]·W[h*256+e]; grid 8 blocks, atomicAdd (v pre-zeroed)
__global__ __launch_bounds__(256) void vecmat_col_par(
    const float* __restrict__ vec, const float* __restrict__ W, float* __restrict__ o)
{
    int e = threadIdx.x;
    int h0 = blockIdx.x * 128;
    float acc = 0.f;
#pragma unroll 8
    for (int h = 0; h < 128; h++) acc += vec[h0 + h] * W[(h0 + h) * 256 + e];
    atomicAdd(&o[e], acc);
}

// q[o] = sum_h vec[h]·W[o*1024+h]
__global__ void vecmat_row(const float* __restrict__ vec, const float* __restrict__ W,
                           float* __restrict__ o)
{
    int ob = blockIdx.x, lane = threadIdx.x;
    float acc = 0.f;
    for (int h = lane; h < 1024; h += 32) acc += vec[h] * W[ob * 1024 + h];
#pragma unroll
    for (int of = 16; of > 0; of >>= 1) acc += __shfl_xor_sync(0xffffffffu, acc, of);
    if (lane == 0) o[ob] = acc;
}

// b[k] = sum_e Q[k*256+e]·v[e]
__global__ __launch_bounds__(256) void bvec(const __half* __restrict__ Q,
                                            const float* __restrict__ v,
                                            float* __restrict__ ob)
{
    __shared__ float sv[256];
    sv[threadIdx.x] = v[threadIdx.x];
    __syncthreads();
    int k = blockIdx.x * 256 + threadIdx.x;
    const __half* row = Q + (long long)k * 256;
    float acc = 0.f;
#pragma unroll 16
    for (int e = 0; e < 256; e += 2) {
        __half2 h2 = *(const __half2*)(row + e);
        acc += __low2float(h2) * sv[e] + __high2float(h2) * sv[e + 1];
    }
    ob[k] = acc;
}

// ---------------------------------------------------------------------------
// Row softmax over 2048 fp16 logits -> fp16 weights
// ---------------------------------------------------------------------------
__global__ __launch_bounds__(256) void softmax_h(const __half* __restrict__ d,
                                                 __half* __restrict__ o)
{
    long long row = blockIdx.x;
    const __half* p = d + row * 2048ll;
    __half* q = o + row * 2048ll;
    int t = threadIdx.x;

    float v[8];
    float m = -1e30f;
#pragma unroll
    for (int j = 0; j < 8; j++) { v[j] = __half2float(p[t + (j << 8)]); m = fmaxf(m, v[j]); }
#pragma unroll
    for (int of = 16; of > 0; of >>= 1) m = fmaxf(m, __shfl_xor_sync(0xffffffffu, m, of));
    __shared__ float redm[8];
    if ((t & 31) == 0) redm[t >> 5] = m;
    __syncthreads();
#pragma unroll
    for (int w2 = 0; w2 < 8; w2++) m = fmaxf(m, redm[w2]);

    float s = 0.f;
#pragma unroll
    for (int j = 0; j < 8; j++) { v[j] = __expf(v[j] - m); s += v[j]; }
#pragma unroll
    for (int of = 16; of > 0; of >>= 1) s += __shfl_xor_sync(0xffffffffu, s, of);
    __shared__ float reds[8];
    if ((t & 31) == 0) reds[t >> 5] = s;
    __syncthreads();
    s = 0.f;
#pragma unroll
    for (int w2 = 0; w2 < 8; w2++) s += reds[w2];
    float inv = 1.f / s;
#pragma unroll
    for (int j = 0; j < 8; j++) q[t + (j << 8)] = __float2half_rn(v[j] * inv);
}

// ---------------------------------------------------------------------------
extern "C" void kernel_launch(void* const* d_in, const int* in_sizes, int n_in,
                              void* d_out, int out_size)
{
    const int Bb = 8, NK = 2048, NQ = 2048, D = 256, H = 1024;
    const float scale = 1.0f / 32.0f;

    const float* KEY   = (const float*)d_in[0];
    const float* VALUE = (const float*)d_in[1];
    const float* QUERY = (const float*)d_in[2];
    const float* Wk_w  = (const float*)d_in[3];
    const float* Wk_b  = (const float*)d_in[4];
    const float* Wq_w  = (const float*)d_in[5];
    const float* Wq_b  = (const float*)d_in[6];
    const float* Wv_w  = (const float*)d_in[7];
    const float* Wv_b  = (const float*)d_in[8];
    const float* lin_w = (const float*)d_in[9];
    const float* lin_b = (const float*)d_in[10];
    float* out = (float*)d_out;
    (void)Wq_b;  // enters only via row-constant terms that cancel in softmax

    __half *key, *val, *qry, *G2, *P2, *KG, *VP, *dist, *w;
    float *G2f, *P2f, *vv, *qq, *bb;
    cudaGetSymbolAddress((void**)&key, h_key);
    cudaGetSymbolAddress((void**)&val, h_val);
    cudaGetSymbolAddress((void**)&qry, h_qry);
    cudaGetSymbolAddress((void**)&G2f, g_G2f);
    cudaGetSymbolAddress((void**)&P2f, g_P2f);
    cudaGetSymbolAddress((void**)&G2, h_G2);
    cudaGetSymbolAddress((void**)&P2, h_P2);
    cudaGetSymbolAddress((void**)&vv, g_v);
    cudaGetSymbolAddress((void**)&qq, g_q);
    cudaGetSymbolAddress((void**)&bb, g_b);
    cudaGetSymbolAddress((void**)&KG, h_KG);
    cudaGetSymbolAddress((void**)&VP, h_VP);
    cudaGetSymbolAddress((void**)&dist, h_dist);
    cudaGetSymbolAddress((void**)&w, h_w);

    (void)cudaFuncSetAttribute(gemm_h<0>, cudaFuncAttributeMaxDynamicSharedMemorySize, SMEM_REQ);
    (void)cudaFuncSetAttribute(gemm_h<1>, cudaFuncAttributeMaxDynamicSharedMemorySize, SMEM_REQ);
    (void)cudaFuncSetAttribute(gemm_h<3>, cudaFuncAttributeMaxDynamicSharedMemorySize, SMEM_REQ);
    (void)cudaFuncSetAttribute(gemm_tn_res, cudaFuncAttributeMaxDynamicSharedMemorySize, SMEM_REQ);

    // fp16 copies of KEY/VALUE/QUERY (one merged launch)
    {
        int n8 = Bb * NK * D / 8;
        cvt_h3<<<dim3((n8 + 255) / 256, 3, 1), 256>>>(KEY, key, VALUE, val, QUERY, qry, n8);
    }

    // Folded weight products (merged split-K, co-scheduled) + bias vectors
    cudaMemsetAsync(G2f, 0, 256 * 256 * sizeof(float), 0);
    cudaMemsetAsync(P2f, 0, 256 * 256 * sizeof(float), 0);
    cudaMemsetAsync(vv, 0, 256 * sizeof(float), 0);
    small_gemm_splitk2<<<dim3(8, 8, 32), 256>>>(Wq_w, Wk_w, lin_w, Wv_w, G2f, P2f);
    cvt_h2<<<dim3((256 * 256 / 8 + 255) / 256, 2, 1), 256>>>(G2f, G2, P2f, P2, 256 * 256 / 8);

    vecmat_col_par<<<8, 256>>>(Wk_b, Wq_w, vv);          // v[e]
    vecmat_row<<<256, 32>>>(Wv_b, lin_w, qq);            // q[o]
    bvec<<<Bb * NQ / 256, 256>>>(qry, vv, bb);           // b[k]

    dim3 thr(256);

    // KG = key·G2^T  (separate launches, as in the known-good R10 binary)
    gemm_h<3><<<dim3(2, 128, 1), thr, SMEM_REQ>>>(
        key, G2, KG, nullptr, Bb * NK, 256, 256, 1.f, 0, 0, 0, 0);

    // VP = val·P2^T + q
    gemm_h<0><<<dim3(2, 128, 1), thr, SMEM_REQ>>>(
        val, P2, VP, qq, Bb * NK, 256, 256, 1.f, 0, 0, 0, 0);

    // dist[b,i,k] = scale*(KG·Q^T + b[k]) -> fp16, batched
    gemm_h<1><<<dim3(16, 16, Bb), thr, SMEM_REQ>>>(
        KG, qry, dist, bb, NK, NQ, 256, scale,
        (long long)NK * 256, (long long)NQ * 256, (long long)NK * NQ, NQ);

    // softmax over k -> fp16 w[i,k]
    softmax_h<<<Bb * NK, 256>>>(dist, w);

    // res[b,k,o] = sum_i w[i,k]·VP[i,o] + lin_b -> fp32 out
    gemm_tn_res<<<dim3(2, 16, Bb), thr, SMEM_REQ>>>(
        w, VP, out, lin_b, NQ, 256, NK,
        (long long)NK * NQ, (long long)NK * 256, (long long)NQ * 256);
}